// round 13
// baseline (speedup 1.0000x reference)
#include <cuda_runtime.h>
#include <cuda_fp16.h>
#include <math.h>
#include <stdint.h>
#include <stddef.h>

#define DEV __device__ __forceinline__

constexpr int Bc = 2, Sc = 2048, Dc = 512, Hc = 8, HDc = 64, KC = 31;
constexpr int FFc = 2048, Gc = 4, Ec = 2;
constexpr int Nc = Bc * Sc; // 4096 tokens

// ---------------- scratch ----------------
__device__ __align__(256) float g_x1[Nc * Dc];
__device__ __align__(256) float g_x2[Nc * Dc];
__device__ __align__(256) __half hh1[Nc * Dc];
__device__ __align__(256) __half hh2[Nc * Dc];
__device__ __align__(256) __half hq[Nc * Dc];
__device__ __align__(256) __half hk[Nc * Dc];
__device__ __align__(256) __half hv[Nc * Dc];
__device__ __align__(256) __half ho[Nc * Dc];
__device__ __align__(256) __half hx2[Nc * Dc];
__device__ __align__(256) __half hhid[(size_t)Nc * Ec * FFc];
// half weights, native [k][n] layouts
__device__ __align__(256) __half hck[(size_t)KC * Dc * Dc];          // [15872][512]
__device__ __align__(256) __half hwq[Dc * Dc];
__device__ __align__(256) __half hwk[Dc * Dc];
__device__ __align__(256) __half hwv[Dc * Dc];
__device__ __align__(256) __half hwo[Dc * Dc];
__device__ __align__(256) __half hw1[(size_t)Gc * Ec * Dc * FFc];    // [g,e][512][2048]
__device__ __align__(256) __half hw2[(size_t)Gc * Ec * FFc * Dc];    // [g][4096][512]
__device__ int g_perm[Gc * Nc];
__device__ int g_cnt[Gc];

DEV float gelu_f(float x) {
    const float c0 = 0.7978845608028654f;
    float t = c0 * (x + 0.044715f * x * x * x);
    return 0.5f * x * (1.0f + tanhf(t));
}

// ---------------- low-level helpers ----------------
DEV void cp16(uint32_t dst, const void* src) {
    asm volatile("cp.async.cg.shared.global [%0], [%1], 16;\n" :: "r"(dst), "l"(src));
}
DEV void cp16z(uint32_t dst, const void* src, bool pred) {
    int sz = pred ? 16 : 0;
    asm volatile("cp.async.cg.shared.global [%0], [%1], 16, %2;\n"
                 :: "r"(dst), "l"(src), "r"(sz));
}
DEV void cp_commit() { asm volatile("cp.async.commit_group;\n"); }
template <int N> DEV void cp_wait() { asm volatile("cp.async.wait_group %0;\n" :: "n"(N)); }
DEV uint32_t smem_u32(const void* p) { return (uint32_t)__cvta_generic_to_shared(p); }
DEV uint32_t packh2(float lo, float hi) {
    __half2 h = __floats2half2_rn(lo, hi);
    return *reinterpret_cast<uint32_t*>(&h);
}
DEV void mma_f16(float (&c)[4], const uint32_t (&a)[4], const uint32_t (&b)[2]) {
    asm volatile(
        "mma.sync.aligned.m16n8k16.row.col.f32.f16.f16.f32 "
        "{%0,%1,%2,%3},{%4,%5,%6,%7},{%8,%9},{%0,%1,%2,%3};\n"
        : "+f"(c[0]), "+f"(c[1]), "+f"(c[2]), "+f"(c[3])
        : "r"(a[0]), "r"(a[1]), "r"(a[2]), "r"(a[3]), "r"(b[0]), "r"(b[1]));
}
DEV void ldm_x4(uint32_t (&r)[4], uint32_t addr) {
    asm volatile("ldmatrix.sync.aligned.m8n8.x4.shared.b16 {%0,%1,%2,%3}, [%4];"
                 : "=r"(r[0]), "=r"(r[1]), "=r"(r[2]), "=r"(r[3]) : "r"(addr));
}
DEV void ldm_x4t(uint32_t (&r)[4], uint32_t addr) {
    asm volatile("ldmatrix.sync.aligned.m8n8.x4.trans.shared.b16 {%0,%1,%2,%3}, [%4];"
                 : "=r"(r[0]), "=r"(r[1]), "=r"(r[2]), "=r"(r[3]) : "r"(addr));
}

// ---------------- f32 -> f16 streaming convert ----------------
__global__ void cvt_kernel(const float* __restrict__ src, __half* __restrict__ dst,
                           int n4) { // n4 = elements/4
    int i = blockIdx.x * blockDim.x + threadIdx.x;
    int stride = gridDim.x * blockDim.x;
    for (; i < n4; i += stride) {
        float4 v = reinterpret_cast<const float4*>(src)[i];
        __half2 lo = __floats2half2_rn(v.x, v.y);
        __half2 hi = __floats2half2_rn(v.z, v.w);
        uint2 o;
        o.x = *reinterpret_cast<uint32_t*>(&lo);
        o.y = *reinterpret_cast<uint32_t*>(&hi);
        reinterpret_cast<uint2*>(dst)[i] = o;
    }
}

// ---------------- LayerNorm ----------------
template <int WHICH>
__global__ void ln_kernel(const float* __restrict__ xin,
                          const float* __restrict__ sc,
                          const float* __restrict__ bi) {
    const float* src = (WHICH == 0) ? xin : g_x1;
    __half* dst = (WHICH == 0) ? hh1 : hh2;
    int row = blockIdx.x;
    const float* xr = src + (size_t)row * Dc;
    __half* orow = dst + (size_t)row * Dc;
    int t = threadIdx.x;
    float a = xr[t], b = xr[t + 256];
    float s = a + b, sq = a * a + b * b;
    __shared__ float sh[16];
#pragma unroll
    for (int o = 16; o; o >>= 1) {
        s += __shfl_xor_sync(0xffffffffu, s, o);
        sq += __shfl_xor_sync(0xffffffffu, sq, o);
    }
    int w = t >> 5;
    if ((t & 31) == 0) { sh[w] = s; sh[8 + w] = sq; }
    __syncthreads();
    if (t == 0) {
        float ts = 0.f, tq = 0.f;
#pragma unroll
        for (int i = 0; i < 8; i++) { ts += sh[i]; tq += sh[8 + i]; }
        float mean = ts * (1.0f / Dc);
        float var = tq * (1.0f / Dc) - mean * mean;
        sh[0] = mean;
        sh[1] = rsqrtf(var + 1e-6f);
    }
    __syncthreads();
    float mean = sh[0], rstd = sh[1];
    orow[t]       = __float2half((a - mean) * rstd * sc[t] + bi[t]);
    orow[t + 256] = __float2half((b - mean) * rstd * sc[t + 256] + bi[t + 256]);
}

// ---------------- routing ----------------
__global__ void zero_cnt_kernel() {
    if (threadIdx.x < Gc) g_cnt[threadIdx.x] = 0;
}
__global__ void scatter_kernel(const int* __restrict__ gid) {
    int n = blockIdx.x * 256 + threadIdx.x;
    if (n < Nc) {
        int g = gid[n];
        int p = atomicAdd(&g_cnt[g], 1);
        g_perm[(g << 12) + p] = n;
    }
}

// ---------------- fused flash attention (fp16 mma.sync) ----------------
constexpr int KVSTR = 72;
__global__ __launch_bounds__(256, 2) void flash_kernel() {
    __shared__ __align__(16) __half Ks[2][64 * KVSTR];
    __shared__ __align__(16) __half Vs[2][64 * KVSTR];
    const int tid = threadIdx.x, lane = tid & 31, warp = tid >> 5;
    const int g = lane >> 2, t4 = lane & 3;
    const int q0 = blockIdx.x * 128;
    const int z = blockIdx.y, b = z >> 3, h = z & 7;
    const int r0 = q0 + warp * 16 + g;

    const __half2* Q2 = reinterpret_cast<const __half2*>(hq);
    size_t qb0 = ((size_t)(b << 11) + r0) * 256 + (h << 5);
    size_t qb1 = qb0 + 8 * 256;
    const __half2 scl = __float2half2_rn(0.125f);
    uint32_t qa[4][4];
#pragma unroll
    for (int ks = 0; ks < 4; ks++) {
        __half2 v0 = __hmul2(Q2[qb0 + ks * 8 + t4], scl);
        __half2 v1 = __hmul2(Q2[qb1 + ks * 8 + t4], scl);
        __half2 v2 = __hmul2(Q2[qb0 + ks * 8 + t4 + 4], scl);
        __half2 v3 = __hmul2(Q2[qb1 + ks * 8 + t4 + 4], scl);
        qa[ks][0] = *reinterpret_cast<uint32_t*>(&v0);
        qa[ks][1] = *reinterpret_cast<uint32_t*>(&v1);
        qa[ks][2] = *reinterpret_cast<uint32_t*>(&v2);
        qa[ks][3] = *reinterpret_cast<uint32_t*>(&v3);
    }

    float m0v = -1e30f, m1v = -1e30f, l0 = 0.f, l1 = 0.f;
    float oacc[8][4];
#pragma unroll
    for (int j = 0; j < 8; j++)
#pragma unroll
        for (int q = 0; q < 4; q++) oacc[j][q] = 0.f;

    const int lrow = tid & 63, lseg = tid >> 6;
    const __half* Kp = hk + (size_t)(b << 11) * Dc + (h << 6);
    const __half* Vp = hv + (size_t)(b << 11) * Dc + (h << 6);
    uint32_t kb0 = smem_u32(&Ks[0][0]), vb0 = smem_u32(&Vs[0][0]);

    auto issueKV = [&](int st, int slot) {
        const __half* kp = Kp + (size_t)(st * 64 + lrow) * Dc;
        const __half* vp = Vp + (size_t)(st * 64 + lrow) * Dc;
        uint32_t kd = kb0 + (uint32_t)((slot * 64 * KVSTR + lrow * KVSTR) * 2);
        uint32_t vd = vb0 + (uint32_t)((slot * 64 * KVSTR + lrow * KVSTR) * 2);
        cp16(kd + lseg * 16, kp + lseg * 8);
        cp16(kd + (lseg + 4) * 16, kp + (lseg + 4) * 8);
        cp16(vd + lseg * 16, vp + lseg * 8);
        cp16(vd + (lseg + 4) * 16, vp + (lseg + 4) * 8);
    };

    issueKV(0, 0);
    cp_commit();
    const float LOG2E = 1.4426950408889634f;

    for (int st = 0; st < 32; st++) {
        cp_wait<0>();
        __syncthreads();
        if (st + 1 < 32) issueKV(st + 1, (st + 1) & 1);
        cp_commit();

        uint32_t kaddr = kb0 + (uint32_t)((st & 1) * 64 * KVSTR * 2);
        uint32_t vaddr = vb0 + (uint32_t)((st & 1) * 64 * KVSTR * 2);

        float sc[8][4];
#pragma unroll
        for (int j = 0; j < 8; j++)
#pragma unroll
            for (int q = 0; q < 4; q++) sc[j][q] = 0.f;
#pragma unroll
        for (int ks = 0; ks < 4; ks++) {
            int kk = ks * 16;
#pragma unroll
            for (int nbp = 0; nbp < 4; nbp++) {
                uint32_t r[4];
                uint32_t addr = kaddr +
                    (uint32_t)(((nbp * 16 + ((lane >> 4) << 3) + (lane & 7)) * KVSTR +
                                kk + (lane & 8)) * 2);
                ldm_x4(r, addr);
                uint32_t b0[2] = {r[0], r[1]}, b1[2] = {r[2], r[3]};
                mma_f16(sc[nbp * 2], qa[ks], b0);
                mma_f16(sc[nbp * 2 + 1], qa[ks], b1);
            }
        }

        float mx0 = m0v, mx1 = m1v;
#pragma unroll
        for (int j = 0; j < 8; j++) {
            mx0 = fmaxf(mx0, fmaxf(sc[j][0], sc[j][1]));
            mx1 = fmaxf(mx1, fmaxf(sc[j][2], sc[j][3]));
        }
        mx0 = fmaxf(mx0, __shfl_xor_sync(0xffffffffu, mx0, 1));
        mx0 = fmaxf(mx0, __shfl_xor_sync(0xffffffffu, mx0, 2));
        mx1 = fmaxf(mx1, __shfl_xor_sync(0xffffffffu, mx1, 1));
        mx1 = fmaxf(mx1, __shfl_xor_sync(0xffffffffu, mx1, 2));
        float al0 = exp2f((m0v - mx0) * LOG2E);
        float al1 = exp2f((m1v - mx1) * LOG2E);
        m0v = mx0; m1v = mx1;
        float s0 = 0.f, s1 = 0.f;
#pragma unroll
        for (int j = 0; j < 8; j++) {
            sc[j][0] = exp2f((sc[j][0] - mx0) * LOG2E);
            sc[j][1] = exp2f((sc[j][1] - mx0) * LOG2E);
            sc[j][2] = exp2f((sc[j][2] - mx1) * LOG2E);
            sc[j][3] = exp2f((sc[j][3] - mx1) * LOG2E);
            s0 += sc[j][0] + sc[j][1];
            s1 += sc[j][2] + sc[j][3];
        }
        s0 += __shfl_xor_sync(0xffffffffu, s0, 1);
        s0 += __shfl_xor_sync(0xffffffffu, s0, 2);
        s1 += __shfl_xor_sync(0xffffffffu, s1, 1);
        s1 += __shfl_xor_sync(0xffffffffu, s1, 2);
        l0 = l0 * al0 + s0;
        l1 = l1 * al1 + s1;
#pragma unroll
        for (int j = 0; j < 8; j++) {
            oacc[j][0] *= al0; oacc[j][1] *= al0;
            oacc[j][2] *= al1; oacc[j][3] *= al1;
        }

#pragma unroll
        for (int ks = 0; ks < 4; ks++) {
            uint32_t pa[4];
            pa[0] = packh2(sc[2 * ks][0], sc[2 * ks][1]);
            pa[1] = packh2(sc[2 * ks][2], sc[2 * ks][3]);
            pa[2] = packh2(sc[2 * ks + 1][0], sc[2 * ks + 1][1]);
            pa[3] = packh2(sc[2 * ks + 1][2], sc[2 * ks + 1][3]);
#pragma unroll
            for (int hdp = 0; hdp < 4; hdp++) {
                uint32_t r[4];
                uint32_t addr = vaddr +
                    (uint32_t)(((ks * 16 + (lane & 15)) * KVSTR +
                                hdp * 16 + ((lane >> 4) << 3)) * 2);
                ldm_x4t(r, addr);
                uint32_t b0[2] = {r[0], r[1]}, b1[2] = {r[2], r[3]};
                mma_f16(oacc[hdp * 2], pa, b0);
                mma_f16(oacc[hdp * 2 + 1], pa, b1);
            }
        }
        __syncthreads();
    }

    float inv0 = 1.0f / l0, inv1 = 1.0f / l1;
    size_t ro0 = ((size_t)(b << 11) + r0) * Dc + (h << 6);
    size_t ro1 = ro0 + (size_t)8 * Dc;
#pragma unroll
    for (int jo = 0; jo < 8; jo++) {
        int c = jo * 8 + 2 * t4;
        ho[ro0 + c]     = __float2half(oacc[jo][0] * inv0);
        ho[ro0 + c + 1] = __float2half(oacc[jo][1] * inv0);
        ho[ro1 + c]     = __float2half(oacc[jo][2] * inv1);
        ho[ro1 + c + 1] = __float2half(oacc[jo][3] * inv1);
    }
}

// ---------------- fp16 GEMM: 64x128 tile, BK=64, 4-stage cp.async, 2 CTAs/SM ----------------
// 32 MMAs per sync boundary; each 16-half chunk = TWO 16-byte cp.async (bug fixed).
constexpr int ASTR = 72;                 // 64 + 8 pad (halves per A row)
constexpr int BSTR = 136;                // 128 + 8 pad (halves per B k-row)
constexpr int A_ST = 64 * ASTR;          // halves
constexpr int B_ST = 64 * BSTR;          // halves
constexpr int STG_H = A_ST + B_ST;       // halves per stage
constexpr int GS = 4;
constexpr size_t GEMM_SMEM = (size_t)GS * STG_H * sizeof(__half); // 106496 B

DEV uint32_t stA(uint32_t sm0, int s) { return sm0 + (uint32_t)(s * STG_H * 2); }
DEV uint32_t stB(uint32_t sm0, int s) { return sm0 + (uint32_t)((s * STG_H + A_ST) * 2); }

// A fill: 64 rows x 64 halves; thread -> row tid>>2, 16 halves (32 B = 2 cp16) at (tid&3)*16
DEV void cpA_dense(uint32_t base, const __half* __restrict__ W, size_t ld,
                   int m0, int k0, int tid) {
    int row = tid >> 2, kh = (tid & 3) << 4;
    const __half* src = W + (size_t)(m0 + row) * ld + k0 + kh;
    uint32_t d = base + (uint32_t)((row * ASTR + kh) * 2);
    cp16(d, src);
    cp16(d + 16, src + 8);
}
// B fill: 64 k-rows x 128 halves; thread -> rows tid>>3 and (tid>>3)+32,
// 16 halves (2 cp16) at (tid&7)*16 in each row => 4 cp16/thread
DEV void cpB_dense(uint32_t base, const __half* __restrict__ W, size_t ldn,
                   int n0, int k0, int tid) {
    int r0w = tid >> 3, nh = (tid & 7) << 4;
    const __half* s0 = W + (size_t)(k0 + r0w) * ldn + n0 + nh;
    uint32_t d0 = base + (uint32_t)((r0w * BSTR + nh) * 2);
    cp16(d0, s0);
    cp16(d0 + 16, s0 + 8);
    int r1w = r0w + 32;
    const __half* s1 = W + (size_t)(k0 + r1w) * ldn + n0 + nh;
    uint32_t d1 = base + (uint32_t)((r1w * BSTR + nh) * 2);
    cp16(d1, s1);
    cp16(d1 + 16, s1 + 8);
}

template <class P>
__global__ __launch_bounds__(256, 2) void gemm_h(P p) {
    if (p.skip()) return;
    extern __shared__ __align__(16) char dynsm[];
    uint32_t sm0 = smem_u32(dynsm);

    int tid = threadIdx.x, lane = tid & 31, warp = tid >> 5;
    int m0 = blockIdx.y * 64, n0 = blockIdx.x * 128, z = blockIdx.z;
    int wm = warp >> 2, wn = warp & 3;   // 2 x 4 warps, warptile 32x32
    int g = lane >> 2, t4 = lane & 3;

    float acc[2][4][4];
#pragma unroll
    for (int i = 0; i < 2; i++)
#pragma unroll
        for (int j = 0; j < 4; j++)
#pragma unroll
            for (int q = 0; q < 4; q++) acc[i][j][q] = 0.f;

    int T = p.K() >> 6;                  // BK = 64
#pragma unroll
    for (int s = 0; s < GS - 1; s++) {
        p.cpA(stA(sm0, s), m0, s * 64, tid, z);
        p.cpB(stB(sm0, s), n0, s * 64, tid, z);
        cp_commit();
    }

    int a_r = lane & 15, a_c = (lane >> 4) << 3;
    int b_kr = lane & 15, b_nc = (lane >> 4) << 3;

    int cur = 0, nxt = GS - 1;
    for (int t = 0; t < T; t++) {
        cp_wait<GS - 2>();
        __syncthreads();
        if (t + GS - 1 < T) {
            p.cpA(stA(sm0, nxt), m0, (t + GS - 1) * 64, tid, z);
            p.cpB(stB(sm0, nxt), n0, (t + GS - 1) * 64, tid, z);
        }
        cp_commit();

        uint32_t ab = stA(sm0, cur);
        uint32_t bb = stB(sm0, cur);
        cur = (cur + 1 == GS) ? 0 : cur + 1;
        nxt = (nxt + 1 == GS) ? 0 : nxt + 1;
#pragma unroll
        for (int ks = 0; ks < 4; ks++) {
            int kk = ks * 16;
            uint32_t af[2][4];
#pragma unroll
            for (int mi = 0; mi < 2; mi++) {
                uint32_t addr = ab +
                    (uint32_t)(((wm * 32 + mi * 16 + a_r) * ASTR + kk + a_c) * 2);
                ldm_x4(af[mi], addr);
            }
            uint32_t bf[4][2];
#pragma unroll
            for (int nb = 0; nb < 2; nb++) {
                uint32_t r[4];
                uint32_t addr = bb +
                    (uint32_t)(((kk + b_kr) * BSTR + wn * 32 + nb * 16 + b_nc) * 2);
                ldm_x4t(r, addr);
                bf[nb * 2][0] = r[0]; bf[nb * 2][1] = r[1];
                bf[nb * 2 + 1][0] = r[2]; bf[nb * 2 + 1][1] = r[3];
            }
#pragma unroll
            for (int mi = 0; mi < 2; mi++)
#pragma unroll
                for (int nj = 0; nj < 4; nj++) mma_f16(acc[mi][nj], af[mi], bf[nj]);
        }
    }
#pragma unroll
    for (int mi = 0; mi < 2; mi++) {
        int r0 = m0 + wm * 32 + mi * 16 + g;
#pragma unroll
        for (int nj = 0; nj < 4; nj++) {
            int c = n0 + wn * 32 + nj * 8 + 2 * t4;
            p.store2(r0, c, acc[mi][nj][0], acc[mi][nj][1], z);
            p.store2(r0 + 8, c, acc[mi][nj][2], acc[mi][nj][3], z);
        }
    }
}

// ================= functors =================

struct ConvProb {
    const float* cb;
    const float* xres;
    DEV int K() const { return KC * Dc; }
    DEV bool skip() const { return false; }
    DEV void cpA(uint32_t base, int m0, int k0, int tid, int) const {
        int row = tid >> 2;
        int m = m0 + row;
        int b = m >> 11, s = m & 2047;
        int kh = (tid & 3) << 4;
        int k = k0 + kh;
        int kk = k >> 9, ci = k & 511;   // 16-half chunk never crosses a tap
        int sr = s + kk - 15;
        bool ok = (unsigned)sr < (unsigned)Sc;
        const __half* src = &hh1[(size_t)((b << 11) + (ok ? sr : 0)) * Dc + ci];
        uint32_t d = base + (uint32_t)((row * ASTR + kh) * 2);
        cp16z(d, src, ok);
        cp16z(d + 16, src + 8, ok);
    }
    DEV void cpB(uint32_t base, int n0, int k0, int tid, int) const {
        cpB_dense(base, hck, Dc, n0, k0, tid);
    }
    DEV void store2(int m, int c, float v0, float v1, int) const {
        size_t o = (size_t)m * Dc + c;
        g_x1[o]     = gelu_f(v0 + cb[c])     + xres[o];
        g_x1[o + 1] = gelu_f(v1 + cb[c + 1]) + xres[o + 1];
    }
};

struct QKVProb {
    const float* b[3];
    DEV int K() const { return Dc; }
    DEV bool skip() const { return false; }
    DEV void cpA(uint32_t base, int m0, int k0, int tid, int) const {
        cpA_dense(base, hh2, Dc, m0, k0, tid);
    }
    DEV void cpB(uint32_t base, int n0, int k0, int tid, int z) const {
        const __half* w = (z == 0) ? hwq : (z == 1) ? hwk : hwv;
        cpB_dense(base, w, Dc, n0, k0, tid);
    }
    DEV void store2(int m, int c, float v0, float v1, int z) const {
        __half* o = (z == 0) ? hq : (z == 1) ? hk : hv;
        const float* bias = b[z];
        size_t off = (size_t)m * Dc + c;
        o[off]     = __float2half(v0 + bias[c]);
        o[off + 1] = __float2half(v1 + bias[c + 1]);
    }
};

struct OutProb {
    const float* bo;
    DEV int K() const { return Dc; }
    DEV bool skip() const { return false; }
    DEV void cpA(uint32_t base, int m0, int k0, int tid, int) const {
        cpA_dense(base, ho, Dc, m0, k0, tid);
    }
    DEV void cpB(uint32_t base, int n0, int k0, int tid, int) const {
        cpB_dense(base, hwo, Dc, n0, k0, tid);
    }
    DEV void store2(int m, int c, float v0, float v1, int) const {
        size_t o = (size_t)m * Dc + c;
        float r0 = v0 + bo[c]     + g_x1[o];
        float r1 = v1 + bo[c + 1] + g_x1[o + 1];
        g_x2[o] = r0;     g_x2[o + 1] = r1;
        hx2[o] = __float2half(r0);
        hx2[o + 1] = __float2half(r1);
    }
};

struct Moe1Prob {
    const float* b1;
    DEV int K() const { return Dc; }
    DEV bool skip() const { return (int)(blockIdx.y * 64) >= g_cnt[blockIdx.z >> 1]; }
    DEV void cpA(uint32_t base, int m0, int k0, int tid, int z) const {
        int g = z >> 1;
        int row = tid >> 2;
        int i = m0 + row;
        bool ok = i < g_cnt[g];
        int tok = ok ? g_perm[(g << 12) + i] : 0;
        int kh = (tid & 3) << 4;
        const __half* src = &hx2[(size_t)tok * Dc + k0 + kh];
        uint32_t d = base + (uint32_t)((row * ASTR + kh) * 2);
        cp16z(d, src, ok);
        cp16z(d + 16, src + 8, ok);
    }
    DEV void cpB(uint32_t base, int n0, int k0, int tid, int z) const {
        cpB_dense(base, hw1 + (size_t)z * Dc * FFc, FFc, n0, k0, tid);
    }
    DEV void store2(int idx, int c, float v0, float v1, int z) const {
        int g = z >> 1, e = z & 1;
        if (idx >= g_cnt[g]) return;
        int tok = g_perm[(g << 12) + idx];
        size_t o = (size_t)tok * (Ec * FFc) + (e << 11) + c;
        const float* bb = &b1[(size_t)z * FFc + c];
        hhid[o]     = __float2half(gelu_f(v0 + bb[0]));
        hhid[o + 1] = __float2half(gelu_f(v1 + bb[1]));
    }
};

struct Moe2Prob {
    const float* b2;
    float* out;
    DEV int K() const { return Ec * FFc; }
    DEV bool skip() const { return (int)(blockIdx.y * 64) >= g_cnt[blockIdx.z]; }
    DEV void cpA(uint32_t base, int m0, int k0, int tid, int z) const {
        int g = z;
        int row = tid >> 2;
        int i = m0 + row;
        bool ok = i < g_cnt[g];
        int tok = ok ? g_perm[(g << 12) + i] : 0;
        int kh = (tid & 3) << 4;
        const __half* src = &hhid[(size_t)tok * (Ec * FFc) + k0 + kh];
        uint32_t d = base + (uint32_t)((row * ASTR + kh) * 2);
        cp16z(d, src, ok);
        cp16z(d + 16, src + 8, ok);
    }
    DEV void cpB(uint32_t base, int n0, int k0, int tid, int z) const {
        cpB_dense(base, hw2 + (size_t)z * Ec * FFc * Dc, Dc, n0, k0, tid);
    }
    DEV void store2(int idx, int c, float v0, float v1, int z) const {
        int g = z;
        if (idx >= g_cnt[g]) return;
        int tok = g_perm[(g << 12) + idx];
        size_t o = (size_t)tok * Dc + c;
        float bs0 = b2[(size_t)(g * 2) * Dc + c] + b2[(size_t)(g * 2 + 1) * Dc + c];
        float bs1 = b2[(size_t)(g * 2) * Dc + c + 1] + b2[(size_t)(g * 2 + 1) * Dc + c + 1];
        out[o]     = 0.5f * v0 + 0.5f * bs0 + g_x2[o];
        out[o + 1] = 0.5f * v1 + 0.5f * bs1 + g_x2[o + 1];
    }
};

// ================= launch =================
template <class P>
static void launch_gemm(dim3 grid, const P& p) {
    cudaFuncSetAttribute(gemm_h<P>, cudaFuncAttributeMaxDynamicSharedMemorySize,
                         (int)GEMM_SMEM);
    gemm_h<P><<<grid, 256, GEMM_SMEM>>>(p);
}

static void cvt(const float* s, __half* d, size_t n) {
    int n4 = (int)(n >> 2);
    int grid = (n4 + 255) / 256;
    if (grid > 1184) grid = 1184;
    cvt_kernel<<<grid, 256>>>(s, d, n4);
}

extern "C" void kernel_launch(void* const* d_in, const int* in_sizes, int n_in,
                              void* d_out, int out_size) {
    const float* x    = (const float*)d_in[0];
    const int*   gid  = (const int*)d_in[1];
    const float* ln1s = (const float*)d_in[2];
    const float* ln1b = (const float*)d_in[3];
    const float* ck   = (const float*)d_in[4];
    const float* cb   = (const float*)d_in[5];
    const float* ln2s = (const float*)d_in[6];
    const float* ln2b = (const float*)d_in[7];
    const float* wq   = (const float*)d_in[8];
    const float* bq   = (const float*)d_in[9];
    const float* wk   = (const float*)d_in[10];
    const float* bk   = (const float*)d_in[11];
    const float* wv   = (const float*)d_in[12];
    const float* bv   = (const float*)d_in[13];
    const float* wo   = (const float*)d_in[14];
    const float* bo   = (const float*)d_in[15];
    const float* w1   = (const float*)d_in[16];
    const float* b1   = (const float*)d_in[17];
    const float* w2   = (const float*)d_in[18];
    const float* b2   = (const float*)d_in[19];
    float* out = (float*)d_out;

    __half* d_hck; cudaGetSymbolAddress((void**)&d_hck, hck);
    __half* d_hwq; cudaGetSymbolAddress((void**)&d_hwq, hwq);
    __half* d_hwk; cudaGetSymbolAddress((void**)&d_hwk, hwk);
    __half* d_hwv; cudaGetSymbolAddress((void**)&d_hwv, hwv);
    __half* d_hwo; cudaGetSymbolAddress((void**)&d_hwo, hwo);
    __half* d_hw1; cudaGetSymbolAddress((void**)&d_hw1, hw1);
    __half* d_hw2; cudaGetSymbolAddress((void**)&d_hw2, hw2);

    cvt(ck, d_hck, (size_t)KC * Dc * Dc);
    cvt(wq, d_hwq, (size_t)Dc * Dc);
    cvt(wk, d_hwk, (size_t)Dc * Dc);
    cvt(wv, d_hwv, (size_t)Dc * Dc);
    ln_kernel<0><<<Nc, 256>>>(x, ln1s, ln1b);
    {
        ConvProb p{cb, x};
        launch_gemm(dim3(Dc / 128, Nc / 64, 1), p);
    }
    cvt(wo, d_hwo, (size_t)Dc * Dc);
    cvt(w1, d_hw1, (size_t)Gc * Ec * Dc * FFc);
    cvt(w2, d_hw2, (size_t)Gc * Ec * FFc * Dc);
    ln_kernel<1><<<Nc, 256>>>(x, ln2s, ln2b);
    {
        QKVProb p;
        p.b[0] = bq; p.b[1] = bk; p.b[2] = bv;
        launch_gemm(dim3(Dc / 128, Nc / 64, 3), p);
    }
    flash_kernel<<<dim3(Sc / 128, Bc * Hc), 256>>>();
    {
        OutProb p{bo};
        launch_gemm(dim3(Dc / 128, Nc / 64, 1), p);
    }
    zero_cnt_kernel<<<1, 32>>>();
    scatter_kernel<<<Nc / 256, 256>>>(gid);
    {
        Moe1Prob p{b1};
        launch_gemm(dim3(FFc / 128, Nc / 64, Gc * Ec), p);
    }
    {
        Moe2Prob p{b2, out};
        launch_gemm(dim3(Dc / 128, Nc / 64, Gc), p);
    }
}

// round 14
// speedup vs baseline: 1.1094x; 1.1094x over previous
#include <cuda_runtime.h>
#include <cuda_fp16.h>
#include <math.h>
#include <stdint.h>
#include <stddef.h>

#define DEV __device__ __forceinline__

constexpr int Bc = 2, Sc = 2048, Dc = 512, Hc = 8, HDc = 64, KC = 31;
constexpr int FFc = 2048, Gc = 4, Ec = 2;
constexpr int Nc = Bc * Sc; // 4096 tokens

// ---------------- scratch ----------------
__device__ __align__(256) float g_x1[Nc * Dc];
__device__ __align__(256) float g_x2[Nc * Dc];
__device__ __align__(256) __half hh1[Nc * Dc];
__device__ __align__(256) __half hh2[Nc * Dc];
__device__ __align__(256) __half hq[Nc * Dc];
__device__ __align__(256) __half hk[Nc * Dc];
__device__ __align__(256) __half hv[Nc * Dc];
__device__ __align__(256) __half ho[Nc * Dc];
__device__ __align__(256) __half hx2[Nc * Dc];
__device__ __align__(256) __half hhid[(size_t)Nc * Ec * FFc];
// half weights, native [k][n] layouts
__device__ __align__(256) __half hck[(size_t)KC * Dc * Dc];          // [15872][512]
__device__ __align__(256) __half hwq[Dc * Dc];
__device__ __align__(256) __half hwk[Dc * Dc];
__device__ __align__(256) __half hwv[Dc * Dc];
__device__ __align__(256) __half hwo[Dc * Dc];
__device__ __align__(256) __half hw1[(size_t)Gc * Ec * Dc * FFc];    // [g,e][512][2048]
__device__ __align__(256) __half hw2[(size_t)Gc * Ec * FFc * Dc];    // [g][4096][512]
__device__ int g_perm[Gc * Nc];
__device__ int g_cnt[Gc];

DEV float gelu_f(float x) {
    const float c0 = 0.7978845608028654f;
    float t = c0 * (x + 0.044715f * x * x * x);
    return 0.5f * x * (1.0f + tanhf(t));
}

// ---------------- low-level helpers ----------------
DEV void cp16(uint32_t dst, const void* src) {
    asm volatile("cp.async.cg.shared.global [%0], [%1], 16;\n" :: "r"(dst), "l"(src));
}
DEV void cp16z(uint32_t dst, const void* src, bool pred) {
    int sz = pred ? 16 : 0;
    asm volatile("cp.async.cg.shared.global [%0], [%1], 16, %2;\n"
                 :: "r"(dst), "l"(src), "r"(sz));
}
DEV void cp_commit() { asm volatile("cp.async.commit_group;\n"); }
template <int N> DEV void cp_wait() { asm volatile("cp.async.wait_group %0;\n" :: "n"(N)); }
DEV uint32_t smem_u32(const void* p) { return (uint32_t)__cvta_generic_to_shared(p); }
DEV uint32_t packh2(float lo, float hi) {
    __half2 h = __floats2half2_rn(lo, hi);
    return *reinterpret_cast<uint32_t*>(&h);
}
DEV void mma_f16(float (&c)[4], const uint32_t (&a)[4], const uint32_t (&b)[2]) {
    asm volatile(
        "mma.sync.aligned.m16n8k16.row.col.f32.f16.f16.f32 "
        "{%0,%1,%2,%3},{%4,%5,%6,%7},{%8,%9},{%0,%1,%2,%3};\n"
        : "+f"(c[0]), "+f"(c[1]), "+f"(c[2]), "+f"(c[3])
        : "r"(a[0]), "r"(a[1]), "r"(a[2]), "r"(a[3]), "r"(b[0]), "r"(b[1]));
}
DEV void ldm_x4(uint32_t (&r)[4], uint32_t addr) {
    asm volatile("ldmatrix.sync.aligned.m8n8.x4.shared.b16 {%0,%1,%2,%3}, [%4];"
                 : "=r"(r[0]), "=r"(r[1]), "=r"(r[2]), "=r"(r[3]) : "r"(addr));
}
DEV void ldm_x4t(uint32_t (&r)[4], uint32_t addr) {
    asm volatile("ldmatrix.sync.aligned.m8n8.x4.trans.shared.b16 {%0,%1,%2,%3}, [%4];"
                 : "=r"(r[0]), "=r"(r[1]), "=r"(r[2]), "=r"(r[3]) : "r"(addr));
}

// ---------------- f32 -> f16 streaming convert ----------------
__global__ void cvt_kernel(const float* __restrict__ src, __half* __restrict__ dst,
                           int n4) { // n4 = elements/4
    int i = blockIdx.x * blockDim.x + threadIdx.x;
    int stride = gridDim.x * blockDim.x;
    for (; i < n4; i += stride) {
        float4 v = reinterpret_cast<const float4*>(src)[i];
        __half2 lo = __floats2half2_rn(v.x, v.y);
        __half2 hi = __floats2half2_rn(v.z, v.w);
        uint2 o;
        o.x = *reinterpret_cast<uint32_t*>(&lo);
        o.y = *reinterpret_cast<uint32_t*>(&hi);
        reinterpret_cast<uint2*>(dst)[i] = o;
    }
}

// ---------------- LayerNorm ----------------
template <int WHICH>
__global__ void ln_kernel(const float* __restrict__ xin,
                          const float* __restrict__ sc,
                          const float* __restrict__ bi) {
    const float* src = (WHICH == 0) ? xin : g_x1;
    __half* dst = (WHICH == 0) ? hh1 : hh2;
    int row = blockIdx.x;
    const float* xr = src + (size_t)row * Dc;
    __half* orow = dst + (size_t)row * Dc;
    int t = threadIdx.x;
    float a = xr[t], b = xr[t + 256];
    float s = a + b, sq = a * a + b * b;
    __shared__ float sh[16];
#pragma unroll
    for (int o = 16; o; o >>= 1) {
        s += __shfl_xor_sync(0xffffffffu, s, o);
        sq += __shfl_xor_sync(0xffffffffu, sq, o);
    }
    int w = t >> 5;
    if ((t & 31) == 0) { sh[w] = s; sh[8 + w] = sq; }
    __syncthreads();
    if (t == 0) {
        float ts = 0.f, tq = 0.f;
#pragma unroll
        for (int i = 0; i < 8; i++) { ts += sh[i]; tq += sh[8 + i]; }
        float mean = ts * (1.0f / Dc);
        float var = tq * (1.0f / Dc) - mean * mean;
        sh[0] = mean;
        sh[1] = rsqrtf(var + 1e-6f);
    }
    __syncthreads();
    float mean = sh[0], rstd = sh[1];
    orow[t]       = __float2half((a - mean) * rstd * sc[t] + bi[t]);
    orow[t + 256] = __float2half((b - mean) * rstd * sc[t + 256] + bi[t + 256]);
}

// ---------------- routing ----------------
__global__ void zero_cnt_kernel() {
    if (threadIdx.x < Gc) g_cnt[threadIdx.x] = 0;
}
__global__ void scatter_kernel(const int* __restrict__ gid) {
    int n = blockIdx.x * 256 + threadIdx.x;
    if (n < Nc) {
        int g = gid[n];
        int p = atomicAdd(&g_cnt[g], 1);
        g_perm[(g << 12) + p] = n;
    }
}

// ---------------- fused flash attention (fp16 mma.sync) ----------------
constexpr int KVSTR = 72;
__global__ __launch_bounds__(256, 2) void flash_kernel() {
    __shared__ __align__(16) __half Ks[2][64 * KVSTR];
    __shared__ __align__(16) __half Vs[2][64 * KVSTR];
    const int tid = threadIdx.x, lane = tid & 31, warp = tid >> 5;
    const int g = lane >> 2, t4 = lane & 3;
    const int q0 = blockIdx.x * 128;
    const int z = blockIdx.y, b = z >> 3, h = z & 7;
    const int r0 = q0 + warp * 16 + g;

    const __half2* Q2 = reinterpret_cast<const __half2*>(hq);
    size_t qb0 = ((size_t)(b << 11) + r0) * 256 + (h << 5);
    size_t qb1 = qb0 + 8 * 256;
    const __half2 scl = __float2half2_rn(0.125f);
    uint32_t qa[4][4];
#pragma unroll
    for (int ks = 0; ks < 4; ks++) {
        __half2 v0 = __hmul2(Q2[qb0 + ks * 8 + t4], scl);
        __half2 v1 = __hmul2(Q2[qb1 + ks * 8 + t4], scl);
        __half2 v2 = __hmul2(Q2[qb0 + ks * 8 + t4 + 4], scl);
        __half2 v3 = __hmul2(Q2[qb1 + ks * 8 + t4 + 4], scl);
        qa[ks][0] = *reinterpret_cast<uint32_t*>(&v0);
        qa[ks][1] = *reinterpret_cast<uint32_t*>(&v1);
        qa[ks][2] = *reinterpret_cast<uint32_t*>(&v2);
        qa[ks][3] = *reinterpret_cast<uint32_t*>(&v3);
    }

    float m0v = -1e30f, m1v = -1e30f, l0 = 0.f, l1 = 0.f;
    float oacc[8][4];
#pragma unroll
    for (int j = 0; j < 8; j++)
#pragma unroll
        for (int q = 0; q < 4; q++) oacc[j][q] = 0.f;

    const int lrow = tid & 63, lseg = tid >> 6;
    const __half* Kp = hk + (size_t)(b << 11) * Dc + (h << 6);
    const __half* Vp = hv + (size_t)(b << 11) * Dc + (h << 6);
    uint32_t kb0 = smem_u32(&Ks[0][0]), vb0 = smem_u32(&Vs[0][0]);

    auto issueKV = [&](int st, int slot) {
        const __half* kp = Kp + (size_t)(st * 64 + lrow) * Dc;
        const __half* vp = Vp + (size_t)(st * 64 + lrow) * Dc;
        uint32_t kd = kb0 + (uint32_t)((slot * 64 * KVSTR + lrow * KVSTR) * 2);
        uint32_t vd = vb0 + (uint32_t)((slot * 64 * KVSTR + lrow * KVSTR) * 2);
        cp16(kd + lseg * 16, kp + lseg * 8);
        cp16(kd + (lseg + 4) * 16, kp + (lseg + 4) * 8);
        cp16(vd + lseg * 16, vp + lseg * 8);
        cp16(vd + (lseg + 4) * 16, vp + (lseg + 4) * 8);
    };

    issueKV(0, 0);
    cp_commit();
    const float LOG2E = 1.4426950408889634f;

    for (int st = 0; st < 32; st++) {
        cp_wait<0>();
        __syncthreads();
        if (st + 1 < 32) issueKV(st + 1, (st + 1) & 1);
        cp_commit();

        uint32_t kaddr = kb0 + (uint32_t)((st & 1) * 64 * KVSTR * 2);
        uint32_t vaddr = vb0 + (uint32_t)((st & 1) * 64 * KVSTR * 2);

        float sc[8][4];
#pragma unroll
        for (int j = 0; j < 8; j++)
#pragma unroll
            for (int q = 0; q < 4; q++) sc[j][q] = 0.f;
#pragma unroll
        for (int ks = 0; ks < 4; ks++) {
            int kk = ks * 16;
#pragma unroll
            for (int nbp = 0; nbp < 4; nbp++) {
                uint32_t r[4];
                uint32_t addr = kaddr +
                    (uint32_t)(((nbp * 16 + ((lane >> 4) << 3) + (lane & 7)) * KVSTR +
                                kk + (lane & 8)) * 2);
                ldm_x4(r, addr);
                uint32_t b0[2] = {r[0], r[1]}, b1[2] = {r[2], r[3]};
                mma_f16(sc[nbp * 2], qa[ks], b0);
                mma_f16(sc[nbp * 2 + 1], qa[ks], b1);
            }
        }

        float mx0 = m0v, mx1 = m1v;
#pragma unroll
        for (int j = 0; j < 8; j++) {
            mx0 = fmaxf(mx0, fmaxf(sc[j][0], sc[j][1]));
            mx1 = fmaxf(mx1, fmaxf(sc[j][2], sc[j][3]));
        }
        mx0 = fmaxf(mx0, __shfl_xor_sync(0xffffffffu, mx0, 1));
        mx0 = fmaxf(mx0, __shfl_xor_sync(0xffffffffu, mx0, 2));
        mx1 = fmaxf(mx1, __shfl_xor_sync(0xffffffffu, mx1, 1));
        mx1 = fmaxf(mx1, __shfl_xor_sync(0xffffffffu, mx1, 2));
        float al0 = exp2f((m0v - mx0) * LOG2E);
        float al1 = exp2f((m1v - mx1) * LOG2E);
        m0v = mx0; m1v = mx1;
        float s0 = 0.f, s1 = 0.f;
#pragma unroll
        for (int j = 0; j < 8; j++) {
            sc[j][0] = exp2f((sc[j][0] - mx0) * LOG2E);
            sc[j][1] = exp2f((sc[j][1] - mx0) * LOG2E);
            sc[j][2] = exp2f((sc[j][2] - mx1) * LOG2E);
            sc[j][3] = exp2f((sc[j][3] - mx1) * LOG2E);
            s0 += sc[j][0] + sc[j][1];
            s1 += sc[j][2] + sc[j][3];
        }
        s0 += __shfl_xor_sync(0xffffffffu, s0, 1);
        s0 += __shfl_xor_sync(0xffffffffu, s0, 2);
        s1 += __shfl_xor_sync(0xffffffffu, s1, 1);
        s1 += __shfl_xor_sync(0xffffffffu, s1, 2);
        l0 = l0 * al0 + s0;
        l1 = l1 * al1 + s1;
#pragma unroll
        for (int j = 0; j < 8; j++) {
            oacc[j][0] *= al0; oacc[j][1] *= al0;
            oacc[j][2] *= al1; oacc[j][3] *= al1;
        }

#pragma unroll
        for (int ks = 0; ks < 4; ks++) {
            uint32_t pa[4];
            pa[0] = packh2(sc[2 * ks][0], sc[2 * ks][1]);
            pa[1] = packh2(sc[2 * ks][2], sc[2 * ks][3]);
            pa[2] = packh2(sc[2 * ks + 1][0], sc[2 * ks + 1][1]);
            pa[3] = packh2(sc[2 * ks + 1][2], sc[2 * ks + 1][3]);
#pragma unroll
            for (int hdp = 0; hdp < 4; hdp++) {
                uint32_t r[4];
                uint32_t addr = vaddr +
                    (uint32_t)(((ks * 16 + (lane & 15)) * KVSTR +
                                hdp * 16 + ((lane >> 4) << 3)) * 2);
                ldm_x4t(r, addr);
                uint32_t b0[2] = {r[0], r[1]}, b1[2] = {r[2], r[3]};
                mma_f16(oacc[hdp * 2], pa, b0);
                mma_f16(oacc[hdp * 2 + 1], pa, b1);
            }
        }
        __syncthreads();
    }

    float inv0 = 1.0f / l0, inv1 = 1.0f / l1;
    size_t ro0 = ((size_t)(b << 11) + r0) * Dc + (h << 6);
    size_t ro1 = ro0 + (size_t)8 * Dc;
#pragma unroll
    for (int jo = 0; jo < 8; jo++) {
        int c = jo * 8 + 2 * t4;
        ho[ro0 + c]     = __float2half(oacc[jo][0] * inv0);
        ho[ro0 + c + 1] = __float2half(oacc[jo][1] * inv0);
        ho[ro1 + c]     = __float2half(oacc[jo][2] * inv1);
        ho[ro1 + c + 1] = __float2half(oacc[jo][3] * inv1);
    }
}

// ---------------- fp16 GEMM: 64x128 tile, BK=32, 5-stage cp.async, 2 CTAs/SM ----------------
constexpr int ASTR = 40;
constexpr int BSTR = 136;
constexpr int A_ST = 64 * ASTR;
constexpr int B_ST = 32 * BSTR;
constexpr int STG_H = A_ST + B_ST;
constexpr int GS = 5;
constexpr size_t GEMM_SMEM = (size_t)GS * STG_H * sizeof(__half); // 69120 B

DEV uint32_t stA(uint32_t sm0, int s) { return sm0 + (uint32_t)(s * STG_H * 2); }
DEV uint32_t stB(uint32_t sm0, int s) { return sm0 + (uint32_t)((s * STG_H + A_ST) * 2); }

DEV void cpA_dense(uint32_t base, const __half* __restrict__ W, size_t ld,
                   int m0, int k0, int tid) {
    int row = tid >> 2, kh = (tid & 3) << 3;
    cp16(base + (uint32_t)((row * ASTR + kh) * 2),
         W + (size_t)(m0 + row) * ld + k0 + kh);
}
DEV void cpB_dense(uint32_t base, const __half* __restrict__ W, size_t ldn,
                   int n0, int k0, int tid) {
    int row = tid >> 3, nh = (tid & 7) << 4;
    const __half* src = W + (size_t)(k0 + row) * ldn + n0 + nh;
    uint32_t d = base + (uint32_t)((row * BSTR + nh) * 2);
    cp16(d, src);
    cp16(d + 16, src + 8);
}

template <class P>
__global__ __launch_bounds__(256, 2) void gemm_h(P p) {
    if (p.skip()) return;
    extern __shared__ __align__(16) char dynsm[];
    uint32_t sm0 = smem_u32(dynsm);

    int tid = threadIdx.x, lane = tid & 31, warp = tid >> 5;
    int m0 = blockIdx.y * 64, n0 = blockIdx.x * 128, z = blockIdx.z;
    int wm = warp >> 2, wn = warp & 3;
    int g = lane >> 2, t4 = lane & 3;

    float acc[2][4][4];
#pragma unroll
    for (int i = 0; i < 2; i++)
#pragma unroll
        for (int j = 0; j < 4; j++)
#pragma unroll
            for (int q = 0; q < 4; q++) acc[i][j][q] = 0.f;

    int T = p.K() >> 5;
#pragma unroll
    for (int s = 0; s < GS - 1; s++) {
        p.cpA(stA(sm0, s), m0, s * 32, tid, z);
        p.cpB(stB(sm0, s), n0, s * 32, tid, z);
        cp_commit();
    }

    int a_r = lane & 15, a_c = (lane >> 4) << 3;
    int b_kr = lane & 15, b_nc = (lane >> 4) << 3;

    int cur = 0, nxt = GS - 1;
    for (int t = 0; t < T; t++) {
        cp_wait<GS - 2>();
        __syncthreads();
        if (t + GS - 1 < T) {
            p.cpA(stA(sm0, nxt), m0, (t + GS - 1) * 32, tid, z);
            p.cpB(stB(sm0, nxt), n0, (t + GS - 1) * 32, tid, z);
        }
        cp_commit();

        uint32_t ab = stA(sm0, cur);
        uint32_t bb = stB(sm0, cur);
        cur = (cur + 1 == GS) ? 0 : cur + 1;
        nxt = (nxt + 1 == GS) ? 0 : nxt + 1;

        uint32_t af[2][2][4];
        uint32_t bf[2][4][2];
#pragma unroll
        for (int ks = 0; ks < 2; ks++) {
            int kk = ks * 16;
#pragma unroll
            for (int mi = 0; mi < 2; mi++) {
                uint32_t addr = ab +
                    (uint32_t)(((wm * 32 + mi * 16 + a_r) * ASTR + kk + a_c) * 2);
                ldm_x4(af[ks][mi], addr);
            }
#pragma unroll
            for (int nb = 0; nb < 2; nb++) {
                uint32_t r[4];
                uint32_t addr = bb +
                    (uint32_t)(((kk + b_kr) * BSTR + wn * 32 + nb * 16 + b_nc) * 2);
                ldm_x4t(r, addr);
                bf[ks][nb * 2][0] = r[0]; bf[ks][nb * 2][1] = r[1];
                bf[ks][nb * 2 + 1][0] = r[2]; bf[ks][nb * 2 + 1][1] = r[3];
            }
        }
#pragma unroll
        for (int ks = 0; ks < 2; ks++)
#pragma unroll
            for (int mi = 0; mi < 2; mi++)
#pragma unroll
                for (int nj = 0; nj < 4; nj++)
                    mma_f16(acc[mi][nj], af[ks][mi], bf[ks][nj]);
    }
#pragma unroll
    for (int mi = 0; mi < 2; mi++) {
        int r0 = m0 + wm * 32 + mi * 16 + g;
#pragma unroll
        for (int nj = 0; nj < 4; nj++) {
            int c = n0 + wn * 32 + nj * 8 + 2 * t4;
            p.store2(r0, c, acc[mi][nj][0], acc[mi][nj][1], z);
            p.store2(r0 + 8, c, acc[mi][nj][2], acc[mi][nj][3], z);
        }
    }
}

// ================= functors =================

struct ConvProb {
    const float* cb;
    const float* xres;
    DEV int K() const { return KC * Dc; }
    DEV bool skip() const { return false; }
    DEV void cpA(uint32_t base, int m0, int k0, int tid, int) const {
        int row = tid >> 2;
        int m = m0 + row;
        int b = m >> 11, s = m & 2047;
        int k = k0 + ((tid & 3) << 3);
        int kk = k >> 9, ci = k & 511;
        int sr = s + kk - 15;
        bool ok = (unsigned)sr < (unsigned)Sc;
        const __half* src = &hh1[(size_t)((b << 11) + (ok ? sr : 0)) * Dc + ci];
        cp16z(base + (uint32_t)((row * ASTR + ((tid & 3) << 3)) * 2), src, ok);
    }
    DEV void cpB(uint32_t base, int n0, int k0, int tid, int) const {
        cpB_dense(base, hck, Dc, n0, k0, tid);
    }
    DEV void store2(int m, int c, float v0, float v1, int) const {
        size_t o = (size_t)m * Dc + c;
        g_x1[o]     = gelu_f(v0 + cb[c])     + xres[o];
        g_x1[o + 1] = gelu_f(v1 + cb[c + 1]) + xres[o + 1];
    }
};

struct QKVProb {
    const float* b[3];
    DEV int K() const { return Dc; }
    DEV bool skip() const { return false; }
    DEV void cpA(uint32_t base, int m0, int k0, int tid, int) const {
        cpA_dense(base, hh2, Dc, m0, k0, tid);
    }
    DEV void cpB(uint32_t base, int n0, int k0, int tid, int z) const {
        const __half* w = (z == 0) ? hwq : (z == 1) ? hwk : hwv;
        cpB_dense(base, w, Dc, n0, k0, tid);
    }
    DEV void store2(int m, int c, float v0, float v1, int z) const {
        __half* o = (z == 0) ? hq : (z == 1) ? hk : hv;
        const float* bias = b[z];
        size_t off = (size_t)m * Dc + c;
        o[off]     = __float2half(v0 + bias[c]);
        o[off + 1] = __float2half(v1 + bias[c + 1]);
    }
};

struct OutProb {
    const float* bo;
    DEV int K() const { return Dc; }
    DEV bool skip() const { return false; }
    DEV void cpA(uint32_t base, int m0, int k0, int tid, int) const {
        cpA_dense(base, ho, Dc, m0, k0, tid);
    }
    DEV void cpB(uint32_t base, int n0, int k0, int tid, int) const {
        cpB_dense(base, hwo, Dc, n0, k0, tid);
    }
    DEV void store2(int m, int c, float v0, float v1, int) const {
        size_t o = (size_t)m * Dc + c;
        float r0 = v0 + bo[c]     + g_x1[o];
        float r1 = v1 + bo[c + 1] + g_x1[o + 1];
        g_x2[o] = r0;     g_x2[o + 1] = r1;
        hx2[o] = __float2half(r0);
        hx2[o + 1] = __float2half(r1);
    }
};

struct Moe1Prob {
    const float* b1;
    DEV int K() const { return Dc; }
    DEV bool skip() const { return (int)(blockIdx.y * 64) >= g_cnt[blockIdx.z >> 1]; }
    DEV void cpA(uint32_t base, int m0, int k0, int tid, int z) const {
        int g = z >> 1;
        int row = tid >> 2;
        int i = m0 + row;
        bool ok = i < g_cnt[g];
        int tok = ok ? g_perm[(g << 12) + i] : 0;
        int kh = (tid & 3) << 3;
        cp16z(base + (uint32_t)((row * ASTR + kh) * 2),
              &hx2[(size_t)tok * Dc + k0 + kh], ok);
    }
    DEV void cpB(uint32_t base, int n0, int k0, int tid, int z) const {
        cpB_dense(base, hw1 + (size_t)z * Dc * FFc, FFc, n0, k0, tid);
    }
    DEV void store2(int idx, int c, float v0, float v1, int z) const {
        int g = z >> 1, e = z & 1;
        if (idx >= g_cnt[g]) return;
        int tok = g_perm[(g << 12) + idx];
        size_t o = (size_t)tok * (Ec * FFc) + (e << 11) + c;
        const float* bb = &b1[(size_t)z * FFc + c];
        hhid[o]     = __float2half(gelu_f(v0 + bb[0]));
        hhid[o + 1] = __float2half(gelu_f(v1 + bb[1]));
    }
};

struct Moe2Prob {
    const float* b2;
    float* out;
    DEV int K() const { return Ec * FFc; }
    DEV bool skip() const { return (int)(blockIdx.y * 64) >= g_cnt[blockIdx.z]; }
    DEV void cpA(uint32_t base, int m0, int k0, int tid, int z) const {
        int g = z;
        int row = tid >> 2;
        int i = m0 + row;
        bool ok = i < g_cnt[g];
        int tok = ok ? g_perm[(g << 12) + i] : 0;
        int kh = (tid & 3) << 3;
        cp16z(base + (uint32_t)((row * ASTR + kh) * 2),
              &hhid[(size_t)tok * (Ec * FFc) + k0 + kh], ok);
    }
    DEV void cpB(uint32_t base, int n0, int k0, int tid, int z) const {
        cpB_dense(base, hw2 + (size_t)z * Ec * FFc * Dc, Dc, n0, k0, tid);
    }
    DEV void store2(int idx, int c, float v0, float v1, int z) const {
        int g = z;
        if (idx >= g_cnt[g]) return;
        int tok = g_perm[(g << 12) + idx];
        size_t o = (size_t)tok * Dc + c;
        float bs0 = b2[(size_t)(g * 2) * Dc + c] + b2[(size_t)(g * 2 + 1) * Dc + c];
        float bs1 = b2[(size_t)(g * 2) * Dc + c + 1] + b2[(size_t)(g * 2 + 1) * Dc + c + 1];
        out[o]     = 0.5f * v0 + 0.5f * bs0 + g_x2[o];
        out[o + 1] = 0.5f * v1 + 0.5f * bs1 + g_x2[o + 1];
    }
};

// ================= launch =================
template <class P>
static void launch_gemm(dim3 grid, const P& p) {
    cudaFuncSetAttribute(gemm_h<P>, cudaFuncAttributeMaxDynamicSharedMemorySize,
                         (int)GEMM_SMEM);
    gemm_h<P><<<grid, 256, GEMM_SMEM>>>(p);
}

static void cvt_s(const float* s, __half* d, size_t n, cudaStream_t st) {
    int n4 = (int)(n >> 2);
    int grid = (n4 + 255) / 256;
    if (grid > 1184) grid = 1184;
    cvt_kernel<<<grid, 256, 0, st>>>(s, d, n4);
}

extern "C" void kernel_launch(void* const* d_in, const int* in_sizes, int n_in,
                              void* d_out, int out_size) {
    const float* x    = (const float*)d_in[0];
    const int*   gid  = (const int*)d_in[1];
    const float* ln1s = (const float*)d_in[2];
    const float* ln1b = (const float*)d_in[3];
    const float* ck   = (const float*)d_in[4];
    const float* cb   = (const float*)d_in[5];
    const float* ln2s = (const float*)d_in[6];
    const float* ln2b = (const float*)d_in[7];
    const float* wq   = (const float*)d_in[8];
    const float* bq   = (const float*)d_in[9];
    const float* wk   = (const float*)d_in[10];
    const float* bk   = (const float*)d_in[11];
    const float* wv   = (const float*)d_in[12];
    const float* bv   = (const float*)d_in[13];
    const float* wo   = (const float*)d_in[14];
    const float* bo   = (const float*)d_in[15];
    const float* w1   = (const float*)d_in[16];
    const float* b1   = (const float*)d_in[17];
    const float* w2   = (const float*)d_in[18];
    const float* b2   = (const float*)d_in[19];
    float* out = (float*)d_out;

    __half* d_hck; cudaGetSymbolAddress((void**)&d_hck, hck);
    __half* d_hwq; cudaGetSymbolAddress((void**)&d_hwq, hwq);
    __half* d_hwk; cudaGetSymbolAddress((void**)&d_hwk, hwk);
    __half* d_hwv; cudaGetSymbolAddress((void**)&d_hwv, hwv);
    __half* d_hwo; cudaGetSymbolAddress((void**)&d_hwo, hwo);
    __half* d_hw1; cudaGetSymbolAddress((void**)&d_hw1, hw1);
    __half* d_hw2; cudaGetSymbolAddress((void**)&d_hw2, hw2);

    // side stream + events (created per call; host-side only; intentionally not
    // destroyed here — destroying a forked stream mid-capture would invalidate
    // the harness's graph capture; the few-calls lifetime makes the leak benign)
    cudaStream_t s1;
    cudaStreamCreateWithFlags(&s1, cudaStreamNonBlocking);
    cudaEvent_t evF, evLn1, evQKVw, evWo, evMoe1, evW2;
    cudaEventCreateWithFlags(&evF, cudaEventDisableTiming);
    cudaEventCreateWithFlags(&evLn1, cudaEventDisableTiming);
    cudaEventCreateWithFlags(&evQKVw, cudaEventDisableTiming);
    cudaEventCreateWithFlags(&evWo, cudaEventDisableTiming);
    cudaEventCreateWithFlags(&evMoe1, cudaEventDisableTiming);
    cudaEventCreateWithFlags(&evW2, cudaEventDisableTiming);

    // fork s1 from the main (capture) stream
    cudaEventRecord(evF, 0);
    cudaStreamWaitEvent(s1, evF, 0);

    // ---- side stream: everything independent of the conv GEMM ----
    ln_kernel<0><<<Nc, 256, 0, s1>>>(x, ln1s, ln1b);
    cudaEventRecord(evLn1, s1);
    cvt_s(wq, d_hwq, (size_t)Dc * Dc, s1);
    cvt_s(wk, d_hwk, (size_t)Dc * Dc, s1);
    cvt_s(wv, d_hwv, (size_t)Dc * Dc, s1);
    cudaEventRecord(evQKVw, s1);
    cvt_s(wo, d_hwo, (size_t)Dc * Dc, s1);
    cudaEventRecord(evWo, s1);
    zero_cnt_kernel<<<1, 32, 0, s1>>>();
    scatter_kernel<<<Nc / 256, 256, 0, s1>>>(gid);
    cvt_s(w1, d_hw1, (size_t)Gc * Ec * Dc * FFc, s1);
    cudaEventRecord(evMoe1, s1);
    cvt_s(w2, d_hw2, (size_t)Gc * Ec * FFc * Dc, s1);
    cudaEventRecord(evW2, s1);

    // ---- main stream ----
    cvt_s(ck, d_hck, (size_t)KC * Dc * Dc, 0);
    cudaStreamWaitEvent(0, evLn1, 0);
    {
        ConvProb p{cb, x};
        launch_gemm(dim3(Dc / 128, Nc / 64, 1), p);
    }
    ln_kernel<1><<<Nc, 256>>>(x, ln2s, ln2b);
    cudaStreamWaitEvent(0, evQKVw, 0);
    {
        QKVProb p;
        p.b[0] = bq; p.b[1] = bk; p.b[2] = bv;
        launch_gemm(dim3(Dc / 128, Nc / 64, 3), p);
    }
    flash_kernel<<<dim3(Sc / 128, Bc * Hc), 256>>>();
    cudaStreamWaitEvent(0, evWo, 0);
    {
        OutProb p{bo};
        launch_gemm(dim3(Dc / 128, Nc / 64, 1), p);
    }
    cudaStreamWaitEvent(0, evMoe1, 0);
    {
        Moe1Prob p{b1};
        launch_gemm(dim3(FFc / 128, Nc / 64, Gc * Ec), p);
    }
    cudaStreamWaitEvent(0, evW2, 0);
    {
        Moe2Prob p{b2, out};
        launch_gemm(dim3(Dc / 128, Nc / 64, Gc), p);
    }
}

// round 15
// speedup vs baseline: 1.1117x; 1.0021x over previous
#include <cuda_runtime.h>
#include <cuda_fp16.h>
#include <math.h>
#include <stdint.h>
#include <stddef.h>

#define DEV __device__ __forceinline__

constexpr int Bc = 2, Sc = 2048, Dc = 512, Hc = 8, HDc = 64, KC = 31;
constexpr int FFc = 2048, Gc = 4, Ec = 2;
constexpr int Nc = Bc * Sc; // 4096 tokens

// ---------------- scratch ----------------
__device__ __align__(256) float g_x1[Nc * Dc];
__device__ __align__(256) float g_x2[Nc * Dc];
__device__ __align__(256) __half hh1[Nc * Dc];
__device__ __align__(256) __half hh2[Nc * Dc];
__device__ __align__(256) __half hq[Nc * Dc];
__device__ __align__(256) __half hk[Nc * Dc];
__device__ __align__(256) __half hv[Nc * Dc];
__device__ __align__(256) __half ho[Nc * Dc];
__device__ __align__(256) __half hx2[Nc * Dc];
__device__ __align__(256) __half hhid[(size_t)Nc * Ec * FFc];
// half weights, native [k][n] layouts
__device__ __align__(256) __half hck[(size_t)KC * Dc * Dc];          // [15872][512]
__device__ __align__(256) __half hwq[Dc * Dc];
__device__ __align__(256) __half hwk[Dc * Dc];
__device__ __align__(256) __half hwv[Dc * Dc];
__device__ __align__(256) __half hwo[Dc * Dc];
__device__ __align__(256) __half hw1[(size_t)Gc * Ec * Dc * FFc];    // [g,e][512][2048]
__device__ __align__(256) __half hw2[(size_t)Gc * Ec * FFc * Dc];    // [g][4096][512]
__device__ int g_perm[Gc * Nc];
__device__ int g_cnt[Gc];

DEV float gelu_f(float x) {
    const float c0 = 0.7978845608028654f;
    float t = c0 * (x + 0.044715f * x * x * x);
    return 0.5f * x * (1.0f + tanhf(t));
}

// ---------------- low-level helpers ----------------
DEV void cp16(uint32_t dst, const void* src) {
    asm volatile("cp.async.cg.shared.global [%0], [%1], 16;\n" :: "r"(dst), "l"(src));
}
DEV void cp16z(uint32_t dst, const void* src, bool pred) {
    int sz = pred ? 16 : 0;
    asm volatile("cp.async.cg.shared.global [%0], [%1], 16, %2;\n"
                 :: "r"(dst), "l"(src), "r"(sz));
}
DEV void cp_commit() { asm volatile("cp.async.commit_group;\n"); }
template <int N> DEV void cp_wait() { asm volatile("cp.async.wait_group %0;\n" :: "n"(N)); }
DEV uint32_t smem_u32(const void* p) { return (uint32_t)__cvta_generic_to_shared(p); }
DEV uint32_t packh2(float lo, float hi) {
    __half2 h = __floats2half2_rn(lo, hi);
    return *reinterpret_cast<uint32_t*>(&h);
}
DEV void mma_f16(float (&c)[4], const uint32_t (&a)[4], const uint32_t (&b)[2]) {
    asm volatile(
        "mma.sync.aligned.m16n8k16.row.col.f32.f16.f16.f32 "
        "{%0,%1,%2,%3},{%4,%5,%6,%7},{%8,%9},{%0,%1,%2,%3};\n"
        : "+f"(c[0]), "+f"(c[1]), "+f"(c[2]), "+f"(c[3])
        : "r"(a[0]), "r"(a[1]), "r"(a[2]), "r"(a[3]), "r"(b[0]), "r"(b[1]));
}
DEV void ldm_x4(uint32_t (&r)[4], uint32_t addr) {
    asm volatile("ldmatrix.sync.aligned.m8n8.x4.shared.b16 {%0,%1,%2,%3}, [%4];"
                 : "=r"(r[0]), "=r"(r[1]), "=r"(r[2]), "=r"(r[3]) : "r"(addr));
}
DEV void ldm_x4t(uint32_t (&r)[4], uint32_t addr) {
    asm volatile("ldmatrix.sync.aligned.m8n8.x4.trans.shared.b16 {%0,%1,%2,%3}, [%4];"
                 : "=r"(r[0]), "=r"(r[1]), "=r"(r[2]), "=r"(r[3]) : "r"(addr));
}

// ---------------- f32 -> f16 streaming convert ----------------
__global__ void cvt_kernel(const float* __restrict__ src, __half* __restrict__ dst,
                           int n4) { // n4 = elements/4
    int i = blockIdx.x * blockDim.x + threadIdx.x;
    int stride = gridDim.x * blockDim.x;
    for (; i < n4; i += stride) {
        float4 v = reinterpret_cast<const float4*>(src)[i];
        __half2 lo = __floats2half2_rn(v.x, v.y);
        __half2 hi = __floats2half2_rn(v.z, v.w);
        uint2 o;
        o.x = *reinterpret_cast<uint32_t*>(&lo);
        o.y = *reinterpret_cast<uint32_t*>(&hi);
        reinterpret_cast<uint2*>(dst)[i] = o;
    }
}

// ---------------- LayerNorm ----------------
template <int WHICH>
__global__ void ln_kernel(const float* __restrict__ xin,
                          const float* __restrict__ sc,
                          const float* __restrict__ bi) {
    const float* src = (WHICH == 0) ? xin : g_x1;
    __half* dst = (WHICH == 0) ? hh1 : hh2;
    int row = blockIdx.x;
    const float* xr = src + (size_t)row * Dc;
    __half* orow = dst + (size_t)row * Dc;
    int t = threadIdx.x;
    float a = xr[t], b = xr[t + 256];
    float s = a + b, sq = a * a + b * b;
    __shared__ float sh[16];
#pragma unroll
    for (int o = 16; o; o >>= 1) {
        s += __shfl_xor_sync(0xffffffffu, s, o);
        sq += __shfl_xor_sync(0xffffffffu, sq, o);
    }
    int w = t >> 5;
    if ((t & 31) == 0) { sh[w] = s; sh[8 + w] = sq; }
    __syncthreads();
    if (t == 0) {
        float ts = 0.f, tq = 0.f;
#pragma unroll
        for (int i = 0; i < 8; i++) { ts += sh[i]; tq += sh[8 + i]; }
        float mean = ts * (1.0f / Dc);
        float var = tq * (1.0f / Dc) - mean * mean;
        sh[0] = mean;
        sh[1] = rsqrtf(var + 1e-6f);
    }
    __syncthreads();
    float mean = sh[0], rstd = sh[1];
    orow[t]       = __float2half((a - mean) * rstd * sc[t] + bi[t]);
    orow[t + 256] = __float2half((b - mean) * rstd * sc[t + 256] + bi[t + 256]);
}

// ---------------- routing ----------------
__global__ void zero_cnt_kernel() {
    if (threadIdx.x < Gc) g_cnt[threadIdx.x] = 0;
}
__global__ void scatter_kernel(const int* __restrict__ gid) {
    int n = blockIdx.x * 256 + threadIdx.x;
    if (n < Nc) {
        int g = gid[n];
        int p = atomicAdd(&g_cnt[g], 1);
        g_perm[(g << 12) + p] = n;
    }
}

// ---------------- fused flash attention (fp16 mma.sync, 3-slot KV ring) ----------------
constexpr int KVSTR = 72;
constexpr int KSLOT = 64 * KVSTR;                       // halves per slot
constexpr size_t FLASH_SMEM = (size_t)6 * KSLOT * sizeof(__half); // 3 K + 3 V slots
__global__ __launch_bounds__(256, 2) void flash_kernel() {
    extern __shared__ __align__(16) __half fsm[];
    __half* Ksm = fsm;                 // [3][KSLOT]
    __half* Vsm = fsm + 3 * KSLOT;     // [3][KSLOT]
    const int tid = threadIdx.x, lane = tid & 31, warp = tid >> 5;
    const int g = lane >> 2, t4 = lane & 3;
    const int q0 = blockIdx.x * 128;
    const int z = blockIdx.y, b = z >> 3, h = z & 7;
    const int r0 = q0 + warp * 16 + g;

    const __half2* Q2 = reinterpret_cast<const __half2*>(hq);
    size_t qb0 = ((size_t)(b << 11) + r0) * 256 + (h << 5);
    size_t qb1 = qb0 + 8 * 256;
    const __half2 scl = __float2half2_rn(0.125f);
    uint32_t qa[4][4];
#pragma unroll
    for (int ks = 0; ks < 4; ks++) {
        __half2 v0 = __hmul2(Q2[qb0 + ks * 8 + t4], scl);
        __half2 v1 = __hmul2(Q2[qb1 + ks * 8 + t4], scl);
        __half2 v2 = __hmul2(Q2[qb0 + ks * 8 + t4 + 4], scl);
        __half2 v3 = __hmul2(Q2[qb1 + ks * 8 + t4 + 4], scl);
        qa[ks][0] = *reinterpret_cast<uint32_t*>(&v0);
        qa[ks][1] = *reinterpret_cast<uint32_t*>(&v1);
        qa[ks][2] = *reinterpret_cast<uint32_t*>(&v2);
        qa[ks][3] = *reinterpret_cast<uint32_t*>(&v3);
    }

    float m0v = -1e30f, m1v = -1e30f, l0 = 0.f, l1 = 0.f;
    float oacc[8][4];
#pragma unroll
    for (int j = 0; j < 8; j++)
#pragma unroll
        for (int q = 0; q < 4; q++) oacc[j][q] = 0.f;

    const int lrow = tid & 63, lseg = tid >> 6;
    const __half* Kp = hk + (size_t)(b << 11) * Dc + (h << 6);
    const __half* Vp = hv + (size_t)(b << 11) * Dc + (h << 6);
    uint32_t kb0 = smem_u32(Ksm), vb0 = smem_u32(Vsm);

    auto issueKV = [&](int st, int slot) {
        const __half* kp = Kp + (size_t)(st * 64 + lrow) * Dc;
        const __half* vp = Vp + (size_t)(st * 64 + lrow) * Dc;
        uint32_t kd = kb0 + (uint32_t)((slot * KSLOT + lrow * KVSTR) * 2);
        uint32_t vd = vb0 + (uint32_t)((slot * KSLOT + lrow * KVSTR) * 2);
        cp16(kd + lseg * 16, kp + lseg * 8);
        cp16(kd + (lseg + 4) * 16, kp + (lseg + 4) * 8);
        cp16(vd + lseg * 16, vp + lseg * 8);
        cp16(vd + (lseg + 4) * 16, vp + (lseg + 4) * 8);
    };

    issueKV(0, 0);
    cp_commit();
    issueKV(1, 1);
    cp_commit();
    const float LOG2E = 1.4426950408889634f;

    int slot = 0;
    for (int st = 0; st < 32; st++) {
        cp_wait<1>();          // slot `slot` (tile st) guaranteed complete
        __syncthreads();       // all warps done reading the slot about to be refilled
        if (st + 2 < 32) {
            int wslot = slot + 2;
            if (wslot >= 3) wslot -= 3;
            issueKV(st + 2, wslot);
        }
        cp_commit();           // unconditional: keeps group count == iteration count

        uint32_t kaddr = kb0 + (uint32_t)(slot * KSLOT * 2);
        uint32_t vaddr = vb0 + (uint32_t)(slot * KSLOT * 2);
        slot = (slot == 2) ? 0 : slot + 1;

        float sc[8][4];
#pragma unroll
        for (int j = 0; j < 8; j++)
#pragma unroll
            for (int q = 0; q < 4; q++) sc[j][q] = 0.f;
#pragma unroll
        for (int ks = 0; ks < 4; ks++) {
            int kk = ks * 16;
#pragma unroll
            for (int nbp = 0; nbp < 4; nbp++) {
                uint32_t r[4];
                uint32_t addr = kaddr +
                    (uint32_t)(((nbp * 16 + ((lane >> 4) << 3) + (lane & 7)) * KVSTR +
                                kk + (lane & 8)) * 2);
                ldm_x4(r, addr);
                uint32_t b0[2] = {r[0], r[1]}, b1[2] = {r[2], r[3]};
                mma_f16(sc[nbp * 2], qa[ks], b0);
                mma_f16(sc[nbp * 2 + 1], qa[ks], b1);
            }
        }

        float mx0 = m0v, mx1 = m1v;
#pragma unroll
        for (int j = 0; j < 8; j++) {
            mx0 = fmaxf(mx0, fmaxf(sc[j][0], sc[j][1]));
            mx1 = fmaxf(mx1, fmaxf(sc[j][2], sc[j][3]));
        }
        mx0 = fmaxf(mx0, __shfl_xor_sync(0xffffffffu, mx0, 1));
        mx0 = fmaxf(mx0, __shfl_xor_sync(0xffffffffu, mx0, 2));
        mx1 = fmaxf(mx1, __shfl_xor_sync(0xffffffffu, mx1, 1));
        mx1 = fmaxf(mx1, __shfl_xor_sync(0xffffffffu, mx1, 2));
        float al0 = exp2f((m0v - mx0) * LOG2E);
        float al1 = exp2f((m1v - mx1) * LOG2E);
        m0v = mx0; m1v = mx1;
        float s0 = 0.f, s1 = 0.f;
#pragma unroll
        for (int j = 0; j < 8; j++) {
            sc[j][0] = exp2f((sc[j][0] - mx0) * LOG2E);
            sc[j][1] = exp2f((sc[j][1] - mx0) * LOG2E);
            sc[j][2] = exp2f((sc[j][2] - mx1) * LOG2E);
            sc[j][3] = exp2f((sc[j][3] - mx1) * LOG2E);
            s0 += sc[j][0] + sc[j][1];
            s1 += sc[j][2] + sc[j][3];
        }
        s0 += __shfl_xor_sync(0xffffffffu, s0, 1);
        s0 += __shfl_xor_sync(0xffffffffu, s0, 2);
        s1 += __shfl_xor_sync(0xffffffffu, s1, 1);
        s1 += __shfl_xor_sync(0xffffffffu, s1, 2);
        l0 = l0 * al0 + s0;
        l1 = l1 * al1 + s1;
#pragma unroll
        for (int j = 0; j < 8; j++) {
            oacc[j][0] *= al0; oacc[j][1] *= al0;
            oacc[j][2] *= al1; oacc[j][3] *= al1;
        }

#pragma unroll
        for (int ks = 0; ks < 4; ks++) {
            uint32_t pa[4];
            pa[0] = packh2(sc[2 * ks][0], sc[2 * ks][1]);
            pa[1] = packh2(sc[2 * ks][2], sc[2 * ks][3]);
            pa[2] = packh2(sc[2 * ks + 1][0], sc[2 * ks + 1][1]);
            pa[3] = packh2(sc[2 * ks + 1][2], sc[2 * ks + 1][3]);
#pragma unroll
            for (int hdp = 0; hdp < 4; hdp++) {
                uint32_t r[4];
                uint32_t addr = vaddr +
                    (uint32_t)(((ks * 16 + (lane & 15)) * KVSTR +
                                hdp * 16 + ((lane >> 4) << 3)) * 2);
                ldm_x4t(r, addr);
                uint32_t b0[2] = {r[0], r[1]}, b1[2] = {r[2], r[3]};
                mma_f16(oacc[hdp * 2], pa, b0);
                mma_f16(oacc[hdp * 2 + 1], pa, b1);
            }
        }
        // no bottom sync: next iteration's top sync orders slot reuse
    }

    float inv0 = 1.0f / l0, inv1 = 1.0f / l1;
    size_t ro0 = ((size_t)(b << 11) + r0) * Dc + (h << 6);
    size_t ro1 = ro0 + (size_t)8 * Dc;
#pragma unroll
    for (int jo = 0; jo < 8; jo++) {
        int c = jo * 8 + 2 * t4;
        ho[ro0 + c]     = __float2half(oacc[jo][0] * inv0);
        ho[ro0 + c + 1] = __float2half(oacc[jo][1] * inv0);
        ho[ro1 + c]     = __float2half(oacc[jo][2] * inv1);
        ho[ro1 + c + 1] = __float2half(oacc[jo][3] * inv1);
    }
}

// ---------------- fp16 GEMM: 64x128 tile, BK=32, 5-stage cp.async, 2 CTAs/SM ----------------
constexpr int ASTR = 40;
constexpr int BSTR = 136;
constexpr int A_ST = 64 * ASTR;
constexpr int B_ST = 32 * BSTR;
constexpr int STG_H = A_ST + B_ST;
constexpr int GS = 5;
constexpr size_t GEMM_SMEM = (size_t)GS * STG_H * sizeof(__half); // 69120 B

DEV uint32_t stA(uint32_t sm0, int s) { return sm0 + (uint32_t)(s * STG_H * 2); }
DEV uint32_t stB(uint32_t sm0, int s) { return sm0 + (uint32_t)((s * STG_H + A_ST) * 2); }

DEV void cpA_dense(uint32_t base, const __half* __restrict__ W, size_t ld,
                   int m0, int k0, int tid) {
    int row = tid >> 2, kh = (tid & 3) << 3;
    cp16(base + (uint32_t)((row * ASTR + kh) * 2),
         W + (size_t)(m0 + row) * ld + k0 + kh);
}
DEV void cpB_dense(uint32_t base, const __half* __restrict__ W, size_t ldn,
                   int n0, int k0, int tid) {
    int row = tid >> 3, nh = (tid & 7) << 4;
    const __half* src = W + (size_t)(k0 + row) * ldn + n0 + nh;
    uint32_t d = base + (uint32_t)((row * BSTR + nh) * 2);
    cp16(d, src);
    cp16(d + 16, src + 8);
}

template <class P>
__global__ __launch_bounds__(256, 2) void gemm_h(P p) {
    if (p.skip()) return;
    extern __shared__ __align__(16) char dynsm[];
    uint32_t sm0 = smem_u32(dynsm);

    int tid = threadIdx.x, lane = tid & 31, warp = tid >> 5;
    int m0 = blockIdx.y * 64, n0 = blockIdx.x * 128, z = blockIdx.z;
    int wm = warp >> 2, wn = warp & 3;
    int g = lane >> 2, t4 = lane & 3;

    float acc[2][4][4];
#pragma unroll
    for (int i = 0; i < 2; i++)
#pragma unroll
        for (int j = 0; j < 4; j++)
#pragma unroll
            for (int q = 0; q < 4; q++) acc[i][j][q] = 0.f;

    int T = p.K() >> 5;
#pragma unroll
    for (int s = 0; s < GS - 1; s++) {
        p.cpA(stA(sm0, s), m0, s * 32, tid, z);
        p.cpB(stB(sm0, s), n0, s * 32, tid, z);
        cp_commit();
    }

    int a_r = lane & 15, a_c = (lane >> 4) << 3;
    int b_kr = lane & 15, b_nc = (lane >> 4) << 3;

    int cur = 0, nxt = GS - 1;
    for (int t = 0; t < T; t++) {
        cp_wait<GS - 2>();
        __syncthreads();
        if (t + GS - 1 < T) {
            p.cpA(stA(sm0, nxt), m0, (t + GS - 1) * 32, tid, z);
            p.cpB(stB(sm0, nxt), n0, (t + GS - 1) * 32, tid, z);
        }
        cp_commit();

        uint32_t ab = stA(sm0, cur);
        uint32_t bb = stB(sm0, cur);
        cur = (cur + 1 == GS) ? 0 : cur + 1;
        nxt = (nxt + 1 == GS) ? 0 : nxt + 1;

        uint32_t af[2][2][4];
        uint32_t bf[2][4][2];
#pragma unroll
        for (int ks = 0; ks < 2; ks++) {
            int kk = ks * 16;
#pragma unroll
            for (int mi = 0; mi < 2; mi++) {
                uint32_t addr = ab +
                    (uint32_t)(((wm * 32 + mi * 16 + a_r) * ASTR + kk + a_c) * 2);
                ldm_x4(af[ks][mi], addr);
            }
#pragma unroll
            for (int nb = 0; nb < 2; nb++) {
                uint32_t r[4];
                uint32_t addr = bb +
                    (uint32_t)(((kk + b_kr) * BSTR + wn * 32 + nb * 16 + b_nc) * 2);
                ldm_x4t(r, addr);
                bf[ks][nb * 2][0] = r[0]; bf[ks][nb * 2][1] = r[1];
                bf[ks][nb * 2 + 1][0] = r[2]; bf[ks][nb * 2 + 1][1] = r[3];
            }
        }
#pragma unroll
        for (int ks = 0; ks < 2; ks++)
#pragma unroll
            for (int mi = 0; mi < 2; mi++)
#pragma unroll
                for (int nj = 0; nj < 4; nj++)
                    mma_f16(acc[mi][nj], af[ks][mi], bf[ks][nj]);
    }
#pragma unroll
    for (int mi = 0; mi < 2; mi++) {
        int r0 = m0 + wm * 32 + mi * 16 + g;
#pragma unroll
        for (int nj = 0; nj < 4; nj++) {
            int c = n0 + wn * 32 + nj * 8 + 2 * t4;
            p.store2(r0, c, acc[mi][nj][0], acc[mi][nj][1], z);
            p.store2(r0 + 8, c, acc[mi][nj][2], acc[mi][nj][3], z);
        }
    }
}

// ================= functors =================

struct ConvProb {
    const float* cb;
    const float* xres;
    DEV int K() const { return KC * Dc; }
    DEV bool skip() const { return false; }
    DEV void cpA(uint32_t base, int m0, int k0, int tid, int) const {
        int row = tid >> 2;
        int m = m0 + row;
        int b = m >> 11, s = m & 2047;
        int k = k0 + ((tid & 3) << 3);
        int kk = k >> 9, ci = k & 511;
        int sr = s + kk - 15;
        bool ok = (unsigned)sr < (unsigned)Sc;
        const __half* src = &hh1[(size_t)((b << 11) + (ok ? sr : 0)) * Dc + ci];
        cp16z(base + (uint32_t)((row * ASTR + ((tid & 3) << 3)) * 2), src, ok);
    }
    DEV void cpB(uint32_t base, int n0, int k0, int tid, int) const {
        cpB_dense(base, hck, Dc, n0, k0, tid);
    }
    DEV void store2(int m, int c, float v0, float v1, int) const {
        size_t o = (size_t)m * Dc + c;
        g_x1[o]     = gelu_f(v0 + cb[c])     + xres[o];
        g_x1[o + 1] = gelu_f(v1 + cb[c + 1]) + xres[o + 1];
    }
};

struct QKVProb {
    const float* b[3];
    DEV int K() const { return Dc; }
    DEV bool skip() const { return false; }
    DEV void cpA(uint32_t base, int m0, int k0, int tid, int) const {
        cpA_dense(base, hh2, Dc, m0, k0, tid);
    }
    DEV void cpB(uint32_t base, int n0, int k0, int tid, int z) const {
        const __half* w = (z == 0) ? hwq : (z == 1) ? hwk : hwv;
        cpB_dense(base, w, Dc, n0, k0, tid);
    }
    DEV void store2(int m, int c, float v0, float v1, int z) const {
        __half* o = (z == 0) ? hq : (z == 1) ? hk : hv;
        const float* bias = b[z];
        size_t off = (size_t)m * Dc + c;
        o[off]     = __float2half(v0 + bias[c]);
        o[off + 1] = __float2half(v1 + bias[c + 1]);
    }
};

struct OutProb {
    const float* bo;
    DEV int K() const { return Dc; }
    DEV bool skip() const { return false; }
    DEV void cpA(uint32_t base, int m0, int k0, int tid, int) const {
        cpA_dense(base, ho, Dc, m0, k0, tid);
    }
    DEV void cpB(uint32_t base, int n0, int k0, int tid, int) const {
        cpB_dense(base, hwo, Dc, n0, k0, tid);
    }
    DEV void store2(int m, int c, float v0, float v1, int) const {
        size_t o = (size_t)m * Dc + c;
        float r0 = v0 + bo[c]     + g_x1[o];
        float r1 = v1 + bo[c + 1] + g_x1[o + 1];
        g_x2[o] = r0;     g_x2[o + 1] = r1;
        hx2[o] = __float2half(r0);
        hx2[o + 1] = __float2half(r1);
    }
};

struct Moe1Prob {
    const float* b1;
    DEV int K() const { return Dc; }
    DEV bool skip() const { return (int)(blockIdx.y * 64) >= g_cnt[blockIdx.z >> 1]; }
    DEV void cpA(uint32_t base, int m0, int k0, int tid, int z) const {
        int g = z >> 1;
        int row = tid >> 2;
        int i = m0 + row;
        bool ok = i < g_cnt[g];
        int tok = ok ? g_perm[(g << 12) + i] : 0;
        int kh = (tid & 3) << 3;
        cp16z(base + (uint32_t)((row * ASTR + kh) * 2),
              &hx2[(size_t)tok * Dc + k0 + kh], ok);
    }
    DEV void cpB(uint32_t base, int n0, int k0, int tid, int z) const {
        cpB_dense(base, hw1 + (size_t)z * Dc * FFc, FFc, n0, k0, tid);
    }
    DEV void store2(int idx, int c, float v0, float v1, int z) const {
        int g = z >> 1, e = z & 1;
        if (idx >= g_cnt[g]) return;
        int tok = g_perm[(g << 12) + idx];
        size_t o = (size_t)tok * (Ec * FFc) + (e << 11) + c;
        const float* bb = &b1[(size_t)z * FFc + c];
        hhid[o]     = __float2half(gelu_f(v0 + bb[0]));
        hhid[o + 1] = __float2half(gelu_f(v1 + bb[1]));
    }
};

struct Moe2Prob {
    const float* b2;
    float* out;
    DEV int K() const { return Ec * FFc; }
    DEV bool skip() const { return (int)(blockIdx.y * 64) >= g_cnt[blockIdx.z]; }
    DEV void cpA(uint32_t base, int m0, int k0, int tid, int z) const {
        int g = z;
        int row = tid >> 2;
        int i = m0 + row;
        bool ok = i < g_cnt[g];
        int tok = ok ? g_perm[(g << 12) + i] : 0;
        int kh = (tid & 3) << 3;
        cp16z(base + (uint32_t)((row * ASTR + kh) * 2),
              &hhid[(size_t)tok * (Ec * FFc) + k0 + kh], ok);
    }
    DEV void cpB(uint32_t base, int n0, int k0, int tid, int z) const {
        cpB_dense(base, hw2 + (size_t)z * Ec * FFc * Dc, Dc, n0, k0, tid);
    }
    DEV void store2(int idx, int c, float v0, float v1, int z) const {
        int g = z;
        if (idx >= g_cnt[g]) return;
        int tok = g_perm[(g << 12) + idx];
        size_t o = (size_t)tok * Dc + c;
        float bs0 = b2[(size_t)(g * 2) * Dc + c] + b2[(size_t)(g * 2 + 1) * Dc + c];
        float bs1 = b2[(size_t)(g * 2) * Dc + c + 1] + b2[(size_t)(g * 2 + 1) * Dc + c + 1];
        out[o]     = 0.5f * v0 + 0.5f * bs0 + g_x2[o];
        out[o + 1] = 0.5f * v1 + 0.5f * bs1 + g_x2[o + 1];
    }
};

// ================= launch =================
template <class P>
static void launch_gemm(dim3 grid, const P& p) {
    cudaFuncSetAttribute(gemm_h<P>, cudaFuncAttributeMaxDynamicSharedMemorySize,
                         (int)GEMM_SMEM);
    gemm_h<P><<<grid, 256, GEMM_SMEM>>>(p);
}

static void cvt_s(const float* s, __half* d, size_t n, cudaStream_t st) {
    int n4 = (int)(n >> 2);
    int grid = (n4 + 255) / 256;
    if (grid > 1184) grid = 1184;
    cvt_kernel<<<grid, 256, 0, st>>>(s, d, n4);
}

extern "C" void kernel_launch(void* const* d_in, const int* in_sizes, int n_in,
                              void* d_out, int out_size) {
    const float* x    = (const float*)d_in[0];
    const int*   gid  = (const int*)d_in[1];
    const float* ln1s = (const float*)d_in[2];
    const float* ln1b = (const float*)d_in[3];
    const float* ck   = (const float*)d_in[4];
    const float* cb   = (const float*)d_in[5];
    const float* ln2s = (const float*)d_in[6];
    const float* ln2b = (const float*)d_in[7];
    const float* wq   = (const float*)d_in[8];
    const float* bq   = (const float*)d_in[9];
    const float* wk   = (const float*)d_in[10];
    const float* bk   = (const float*)d_in[11];
    const float* wv   = (const float*)d_in[12];
    const float* bv   = (const float*)d_in[13];
    const float* wo   = (const float*)d_in[14];
    const float* bo   = (const float*)d_in[15];
    const float* w1   = (const float*)d_in[16];
    const float* b1   = (const float*)d_in[17];
    const float* w2   = (const float*)d_in[18];
    const float* b2   = (const float*)d_in[19];
    float* out = (float*)d_out;

    __half* d_hck; cudaGetSymbolAddress((void**)&d_hck, hck);
    __half* d_hwq; cudaGetSymbolAddress((void**)&d_hwq, hwq);
    __half* d_hwk; cudaGetSymbolAddress((void**)&d_hwk, hwk);
    __half* d_hwv; cudaGetSymbolAddress((void**)&d_hwv, hwv);
    __half* d_hwo; cudaGetSymbolAddress((void**)&d_hwo, hwo);
    __half* d_hw1; cudaGetSymbolAddress((void**)&d_hw1, hw1);
    __half* d_hw2; cudaGetSymbolAddress((void**)&d_hw2, hw2);

    // side stream + events (created per call; host-side only; intentionally not
    // destroyed here — destroying a forked stream mid-capture would invalidate
    // the harness's graph capture; the few-calls lifetime makes the leak benign)
    cudaStream_t s1;
    cudaStreamCreateWithFlags(&s1, cudaStreamNonBlocking);
    cudaEvent_t evF, evLn1, evQKVw, evWo, evMoe1, evW2;
    cudaEventCreateWithFlags(&evF, cudaEventDisableTiming);
    cudaEventCreateWithFlags(&evLn1, cudaEventDisableTiming);
    cudaEventCreateWithFlags(&evQKVw, cudaEventDisableTiming);
    cudaEventCreateWithFlags(&evWo, cudaEventDisableTiming);
    cudaEventCreateWithFlags(&evMoe1, cudaEventDisableTiming);
    cudaEventCreateWithFlags(&evW2, cudaEventDisableTiming);

    // fork s1 from the main (capture) stream
    cudaEventRecord(evF, 0);
    cudaStreamWaitEvent(s1, evF, 0);

    // ---- side stream: everything independent of the conv GEMM ----
    ln_kernel<0><<<Nc, 256, 0, s1>>>(x, ln1s, ln1b);
    cudaEventRecord(evLn1, s1);
    cvt_s(wq, d_hwq, (size_t)Dc * Dc, s1);
    cvt_s(wk, d_hwk, (size_t)Dc * Dc, s1);
    cvt_s(wv, d_hwv, (size_t)Dc * Dc, s1);
    cudaEventRecord(evQKVw, s1);
    cvt_s(wo, d_hwo, (size_t)Dc * Dc, s1);
    cudaEventRecord(evWo, s1);
    zero_cnt_kernel<<<1, 32, 0, s1>>>();
    scatter_kernel<<<Nc / 256, 256, 0, s1>>>(gid);
    cvt_s(w1, d_hw1, (size_t)Gc * Ec * Dc * FFc, s1);
    cudaEventRecord(evMoe1, s1);
    cvt_s(w2, d_hw2, (size_t)Gc * Ec * FFc * Dc, s1);
    cudaEventRecord(evW2, s1);

    // ---- main stream ----
    cvt_s(ck, d_hck, (size_t)KC * Dc * Dc, 0);
    cudaStreamWaitEvent(0, evLn1, 0);
    {
        ConvProb p{cb, x};
        launch_gemm(dim3(Dc / 128, Nc / 64, 1), p);
    }
    ln_kernel<1><<<Nc, 256>>>(x, ln2s, ln2b);
    cudaStreamWaitEvent(0, evQKVw, 0);
    {
        QKVProb p;
        p.b[0] = bq; p.b[1] = bk; p.b[2] = bv;
        launch_gemm(dim3(Dc / 128, Nc / 64, 3), p);
    }
    cudaFuncSetAttribute(flash_kernel, cudaFuncAttributeMaxDynamicSharedMemorySize,
                         (int)FLASH_SMEM);
    flash_kernel<<<dim3(Sc / 128, Bc * Hc), 256, FLASH_SMEM>>>();
    cudaStreamWaitEvent(0, evWo, 0);
    {
        OutProb p{bo};
        launch_gemm(dim3(Dc / 128, Nc / 64, 1), p);
    }
    cudaStreamWaitEvent(0, evMoe1, 0);
    {
        Moe1Prob p{b1};
        launch_gemm(dim3(FFc / 128, Nc / 64, Gc * Ec), p);
    }
    cudaStreamWaitEvent(0, evW2, 0);
    {
        Moe2Prob p{b2, out};
        launch_gemm(dim3(Dc / 128, Nc / 64, Gc), p);
    }
}

// round 16
// speedup vs baseline: 1.1188x; 1.0064x over previous
#include <cuda_runtime.h>
#include <cuda_fp16.h>
#include <math.h>
#include <stdint.h>
#include <stddef.h>

#define DEV __device__ __forceinline__

constexpr int Bc = 2, Sc = 2048, Dc = 512, Hc = 8, HDc = 64, KC = 31;
constexpr int FFc = 2048, Gc = 4, Ec = 2;
constexpr int Nc = Bc * Sc; // 4096 tokens

// ---------------- scratch ----------------
__device__ __align__(256) float g_x1[Nc * Dc];
__device__ __align__(256) float g_x2[Nc * Dc];
__device__ __align__(256) __half hh1[Nc * Dc];
__device__ __align__(256) __half hh2[Nc * Dc];
__device__ __align__(256) __half hq[Nc * Dc];
__device__ __align__(256) __half hk[Nc * Dc];
__device__ __align__(256) __half hv[Nc * Dc];
__device__ __align__(256) __half ho[Nc * Dc];
__device__ __align__(256) __half hx2[Nc * Dc];
__device__ __align__(256) __half hhid[(size_t)Nc * Ec * FFc];
// half weights, native [k][n] layouts
__device__ __align__(256) __half hck[(size_t)KC * Dc * Dc];          // [15872][512]
__device__ __align__(256) __half hwqkv[(size_t)Dc * 3 * Dc];         // [512][1536] (q|k|v)
__device__ __align__(256) __half hwo[Dc * Dc];
__device__ __align__(256) __half hw1[(size_t)Gc * Ec * Dc * FFc];    // [g,e][512][2048]
__device__ __align__(256) __half hw2[(size_t)Gc * Ec * FFc * Dc];    // [g][4096][512]
__device__ int g_perm[Gc * Nc];
__device__ int g_cnt[Gc];

DEV float gelu_f(float x) {
    const float c0 = 0.7978845608028654f;
    float t = c0 * (x + 0.044715f * x * x * x);
    return 0.5f * x * (1.0f + tanhf(t));
}

// ---------------- low-level helpers ----------------
DEV void cp16(uint32_t dst, const void* src) {
    asm volatile("cp.async.cg.shared.global [%0], [%1], 16;\n" :: "r"(dst), "l"(src));
}
DEV void cp16z(uint32_t dst, const void* src, bool pred) {
    int sz = pred ? 16 : 0;
    asm volatile("cp.async.cg.shared.global [%0], [%1], 16, %2;\n"
                 :: "r"(dst), "l"(src), "r"(sz));
}
DEV void cp_commit() { asm volatile("cp.async.commit_group;\n"); }
template <int N> DEV void cp_wait() { asm volatile("cp.async.wait_group %0;\n" :: "n"(N)); }
DEV uint32_t smem_u32(const void* p) { return (uint32_t)__cvta_generic_to_shared(p); }
DEV uint32_t packh2(float lo, float hi) {
    __half2 h = __floats2half2_rn(lo, hi);
    return *reinterpret_cast<uint32_t*>(&h);
}
DEV void mma_f16(float (&c)[4], const uint32_t (&a)[4], const uint32_t (&b)[2]) {
    asm volatile(
        "mma.sync.aligned.m16n8k16.row.col.f32.f16.f16.f32 "
        "{%0,%1,%2,%3},{%4,%5,%6,%7},{%8,%9},{%0,%1,%2,%3};\n"
        : "+f"(c[0]), "+f"(c[1]), "+f"(c[2]), "+f"(c[3])
        : "r"(a[0]), "r"(a[1]), "r"(a[2]), "r"(a[3]), "r"(b[0]), "r"(b[1]));
}
DEV void ldm_x4(uint32_t (&r)[4], uint32_t addr) {
    asm volatile("ldmatrix.sync.aligned.m8n8.x4.shared.b16 {%0,%1,%2,%3}, [%4];"
                 : "=r"(r[0]), "=r"(r[1]), "=r"(r[2]), "=r"(r[3]) : "r"(addr));
}
DEV void ldm_x4t(uint32_t (&r)[4], uint32_t addr) {
    asm volatile("ldmatrix.sync.aligned.m8n8.x4.trans.shared.b16 {%0,%1,%2,%3}, [%4];"
                 : "=r"(r[0]), "=r"(r[1]), "=r"(r[2]), "=r"(r[3]) : "r"(addr));
}

// ---------------- f32 -> f16 converts ----------------
__global__ void cvt_kernel(const float* __restrict__ src, __half* __restrict__ dst,
                           int n4) {
    int i = blockIdx.x * blockDim.x + threadIdx.x;
    int stride = gridDim.x * blockDim.x;
    for (; i < n4; i += stride) {
        float4 v = reinterpret_cast<const float4*>(src)[i];
        __half2 lo = __floats2half2_rn(v.x, v.y);
        __half2 hi = __floats2half2_rn(v.z, v.w);
        uint2 o;
        o.x = *reinterpret_cast<uint32_t*>(&lo);
        o.y = *reinterpret_cast<uint32_t*>(&hi);
        reinterpret_cast<uint2*>(dst)[i] = o;
    }
}
// strided dest: src [K][ncols] -> dst rows at dstride, column offset coloff
__global__ void cvts_kernel(const float* __restrict__ src, __half* __restrict__ dst,
                            int ncols, int dstride, int coloff, int n4) {
    int i = blockIdx.x * blockDim.x + threadIdx.x;
    int stride = gridDim.x * blockDim.x;
    for (; i < n4; i += stride) {
        int e = i << 2;
        int row = e / ncols, col = e - row * ncols;
        float4 v = reinterpret_cast<const float4*>(src)[i];
        __half2 lo = __floats2half2_rn(v.x, v.y);
        __half2 hi = __floats2half2_rn(v.z, v.w);
        uint2 o;
        o.x = *reinterpret_cast<uint32_t*>(&lo);
        o.y = *reinterpret_cast<uint32_t*>(&hi);
        *reinterpret_cast<uint2*>(&dst[(size_t)row * dstride + coloff + col]) = o;
    }
}

// ---------------- LayerNorm ----------------
template <int WHICH>
__global__ void ln_kernel(const float* __restrict__ xin,
                          const float* __restrict__ sc,
                          const float* __restrict__ bi) {
    const float* src = (WHICH == 0) ? xin : g_x1;
    __half* dst = (WHICH == 0) ? hh1 : hh2;
    int row = blockIdx.x;
    const float* xr = src + (size_t)row * Dc;
    __half* orow = dst + (size_t)row * Dc;
    int t = threadIdx.x;
    float a = xr[t], b = xr[t + 256];
    float s = a + b, sq = a * a + b * b;
    __shared__ float sh[16];
#pragma unroll
    for (int o = 16; o; o >>= 1) {
        s += __shfl_xor_sync(0xffffffffu, s, o);
        sq += __shfl_xor_sync(0xffffffffu, sq, o);
    }
    int w = t >> 5;
    if ((t & 31) == 0) { sh[w] = s; sh[8 + w] = sq; }
    __syncthreads();
    if (t == 0) {
        float ts = 0.f, tq = 0.f;
#pragma unroll
        for (int i = 0; i < 8; i++) { ts += sh[i]; tq += sh[8 + i]; }
        float mean = ts * (1.0f / Dc);
        float var = tq * (1.0f / Dc) - mean * mean;
        sh[0] = mean;
        sh[1] = rsqrtf(var + 1e-6f);
    }
    __syncthreads();
    float mean = sh[0], rstd = sh[1];
    orow[t]       = __float2half((a - mean) * rstd * sc[t] + bi[t]);
    orow[t + 256] = __float2half((b - mean) * rstd * sc[t + 256] + bi[t + 256]);
}

// ---------------- routing ----------------
__global__ void zero_cnt_kernel() {
    if (threadIdx.x < Gc) g_cnt[threadIdx.x] = 0;
}
__global__ void scatter_kernel(const int* __restrict__ gid) {
    int n = blockIdx.x * 256 + threadIdx.x;
    if (n < Nc) {
        int g = gid[n];
        int p = atomicAdd(&g_cnt[g], 1);
        g_perm[(g << 12) + p] = n;
    }
}

// ---------------- fused flash attention (fp16 mma.sync, 3-slot KV ring) ----------------
constexpr int KVSTR = 72;
constexpr int KSLOT = 64 * KVSTR;
constexpr size_t FLASH_SMEM = (size_t)6 * KSLOT * sizeof(__half);
__global__ __launch_bounds__(256, 2) void flash_kernel() {
    extern __shared__ __align__(16) __half fsm[];
    __half* Ksm = fsm;
    __half* Vsm = fsm + 3 * KSLOT;
    const int tid = threadIdx.x, lane = tid & 31, warp = tid >> 5;
    const int g = lane >> 2, t4 = lane & 3;
    const int q0 = blockIdx.x * 128;
    const int z = blockIdx.y, b = z >> 3, h = z & 7;
    const int r0 = q0 + warp * 16 + g;

    const __half2* Q2 = reinterpret_cast<const __half2*>(hq);
    size_t qb0 = ((size_t)(b << 11) + r0) * 256 + (h << 5);
    size_t qb1 = qb0 + 8 * 256;
    const __half2 scl = __float2half2_rn(0.125f);
    uint32_t qa[4][4];
#pragma unroll
    for (int ks = 0; ks < 4; ks++) {
        __half2 v0 = __hmul2(Q2[qb0 + ks * 8 + t4], scl);
        __half2 v1 = __hmul2(Q2[qb1 + ks * 8 + t4], scl);
        __half2 v2 = __hmul2(Q2[qb0 + ks * 8 + t4 + 4], scl);
        __half2 v3 = __hmul2(Q2[qb1 + ks * 8 + t4 + 4], scl);
        qa[ks][0] = *reinterpret_cast<uint32_t*>(&v0);
        qa[ks][1] = *reinterpret_cast<uint32_t*>(&v1);
        qa[ks][2] = *reinterpret_cast<uint32_t*>(&v2);
        qa[ks][3] = *reinterpret_cast<uint32_t*>(&v3);
    }

    float m0v = -1e30f, m1v = -1e30f, l0 = 0.f, l1 = 0.f;
    float oacc[8][4];
#pragma unroll
    for (int j = 0; j < 8; j++)
#pragma unroll
        for (int q = 0; q < 4; q++) oacc[j][q] = 0.f;

    const int lrow = tid & 63, lseg = tid >> 6;
    const __half* Kp = hk + (size_t)(b << 11) * Dc + (h << 6);
    const __half* Vp = hv + (size_t)(b << 11) * Dc + (h << 6);
    uint32_t kb0 = smem_u32(Ksm), vb0 = smem_u32(Vsm);

    auto issueKV = [&](int st, int slot) {
        const __half* kp = Kp + (size_t)(st * 64 + lrow) * Dc;
        const __half* vp = Vp + (size_t)(st * 64 + lrow) * Dc;
        uint32_t kd = kb0 + (uint32_t)((slot * KSLOT + lrow * KVSTR) * 2);
        uint32_t vd = vb0 + (uint32_t)((slot * KSLOT + lrow * KVSTR) * 2);
        cp16(kd + lseg * 16, kp + lseg * 8);
        cp16(kd + (lseg + 4) * 16, kp + (lseg + 4) * 8);
        cp16(vd + lseg * 16, vp + lseg * 8);
        cp16(vd + (lseg + 4) * 16, vp + (lseg + 4) * 8);
    };

    issueKV(0, 0);
    cp_commit();
    issueKV(1, 1);
    cp_commit();
    const float LOG2E = 1.4426950408889634f;

    int slot = 0;
    for (int st = 0; st < 32; st++) {
        cp_wait<1>();
        __syncthreads();
        if (st + 2 < 32) {
            int wslot = slot + 2;
            if (wslot >= 3) wslot -= 3;
            issueKV(st + 2, wslot);
        }
        cp_commit();

        uint32_t kaddr = kb0 + (uint32_t)(slot * KSLOT * 2);
        uint32_t vaddr = vb0 + (uint32_t)(slot * KSLOT * 2);
        slot = (slot == 2) ? 0 : slot + 1;

        float sc[8][4];
#pragma unroll
        for (int j = 0; j < 8; j++)
#pragma unroll
            for (int q = 0; q < 4; q++) sc[j][q] = 0.f;
#pragma unroll
        for (int ks = 0; ks < 4; ks++) {
            int kk = ks * 16;
#pragma unroll
            for (int nbp = 0; nbp < 4; nbp++) {
                uint32_t r[4];
                uint32_t addr = kaddr +
                    (uint32_t)(((nbp * 16 + ((lane >> 4) << 3) + (lane & 7)) * KVSTR +
                                kk + (lane & 8)) * 2);
                ldm_x4(r, addr);
                uint32_t b0[2] = {r[0], r[1]}, b1[2] = {r[2], r[3]};
                mma_f16(sc[nbp * 2], qa[ks], b0);
                mma_f16(sc[nbp * 2 + 1], qa[ks], b1);
            }
        }

        float mx0 = m0v, mx1 = m1v;
#pragma unroll
        for (int j = 0; j < 8; j++) {
            mx0 = fmaxf(mx0, fmaxf(sc[j][0], sc[j][1]));
            mx1 = fmaxf(mx1, fmaxf(sc[j][2], sc[j][3]));
        }
        mx0 = fmaxf(mx0, __shfl_xor_sync(0xffffffffu, mx0, 1));
        mx0 = fmaxf(mx0, __shfl_xor_sync(0xffffffffu, mx0, 2));
        mx1 = fmaxf(mx1, __shfl_xor_sync(0xffffffffu, mx1, 1));
        mx1 = fmaxf(mx1, __shfl_xor_sync(0xffffffffu, mx1, 2));
        float al0 = exp2f((m0v - mx0) * LOG2E);
        float al1 = exp2f((m1v - mx1) * LOG2E);
        m0v = mx0; m1v = mx1;
        float s0 = 0.f, s1 = 0.f;
#pragma unroll
        for (int j = 0; j < 8; j++) {
            sc[j][0] = exp2f((sc[j][0] - mx0) * LOG2E);
            sc[j][1] = exp2f((sc[j][1] - mx0) * LOG2E);
            sc[j][2] = exp2f((sc[j][2] - mx1) * LOG2E);
            sc[j][3] = exp2f((sc[j][3] - mx1) * LOG2E);
            s0 += sc[j][0] + sc[j][1];
            s1 += sc[j][2] + sc[j][3];
        }
        s0 += __shfl_xor_sync(0xffffffffu, s0, 1);
        s0 += __shfl_xor_sync(0xffffffffu, s0, 2);
        s1 += __shfl_xor_sync(0xffffffffu, s1, 1);
        s1 += __shfl_xor_sync(0xffffffffu, s1, 2);
        l0 = l0 * al0 + s0;
        l1 = l1 * al1 + s1;
#pragma unroll
        for (int j = 0; j < 8; j++) {
            oacc[j][0] *= al0; oacc[j][1] *= al0;
            oacc[j][2] *= al1; oacc[j][3] *= al1;
        }

#pragma unroll
        for (int ks = 0; ks < 4; ks++) {
            uint32_t pa[4];
            pa[0] = packh2(sc[2 * ks][0], sc[2 * ks][1]);
            pa[1] = packh2(sc[2 * ks][2], sc[2 * ks][3]);
            pa[2] = packh2(sc[2 * ks + 1][0], sc[2 * ks + 1][1]);
            pa[3] = packh2(sc[2 * ks + 1][2], sc[2 * ks + 1][3]);
#pragma unroll
            for (int hdp = 0; hdp < 4; hdp++) {
                uint32_t r[4];
                uint32_t addr = vaddr +
                    (uint32_t)(((ks * 16 + (lane & 15)) * KVSTR +
                                hdp * 16 + ((lane >> 4) << 3)) * 2);
                ldm_x4t(r, addr);
                uint32_t b0[2] = {r[0], r[1]}, b1[2] = {r[2], r[3]};
                mma_f16(oacc[hdp * 2], pa, b0);
                mma_f16(oacc[hdp * 2 + 1], pa, b1);
            }
        }
    }

    float inv0 = 1.0f / l0, inv1 = 1.0f / l1;
    size_t ro0 = ((size_t)(b << 11) + r0) * Dc + (h << 6);
    size_t ro1 = ro0 + (size_t)8 * Dc;
#pragma unroll
    for (int jo = 0; jo < 8; jo++) {
        int c = jo * 8 + 2 * t4;
        ho[ro0 + c]     = __float2half(oacc[jo][0] * inv0);
        ho[ro0 + c + 1] = __float2half(oacc[jo][1] * inv0);
        ho[ro1 + c]     = __float2half(oacc[jo][2] * inv1);
        ho[ro1 + c + 1] = __float2half(oacc[jo][3] * inv1);
    }
}

// ---------------- narrow fp16 GEMM: 64x128 tile, BK=32, 5-stage ----------------
constexpr int ASTR = 40;
constexpr int BSTR = 136;
constexpr int A_ST = 64 * ASTR;
constexpr int B_ST = 32 * BSTR;
constexpr int STG_H = A_ST + B_ST;
constexpr int GS = 5;
constexpr size_t GEMM_SMEM = (size_t)GS * STG_H * sizeof(__half);

DEV uint32_t stA(uint32_t sm0, int s) { return sm0 + (uint32_t)(s * STG_H * 2); }
DEV uint32_t stB(uint32_t sm0, int s) { return sm0 + (uint32_t)((s * STG_H + A_ST) * 2); }

DEV void cpA_dense(uint32_t base, const __half* __restrict__ W, size_t ld,
                   int m0, int k0, int tid) {
    int row = tid >> 2, kh = (tid & 3) << 3;
    cp16(base + (uint32_t)((row * ASTR + kh) * 2),
         W + (size_t)(m0 + row) * ld + k0 + kh);
}
DEV void cpB_dense(uint32_t base, const __half* __restrict__ W, size_t ldn,
                   int n0, int k0, int tid) {
    int row = tid >> 3, nh = (tid & 7) << 4;
    const __half* src = W + (size_t)(k0 + row) * ldn + n0 + nh;
    uint32_t d = base + (uint32_t)((row * BSTR + nh) * 2);
    cp16(d, src);
    cp16(d + 16, src + 8);
}

template <class P>
__global__ __launch_bounds__(256, 2) void gemm_h(P p) {
    if (p.skip()) return;
    extern __shared__ __align__(16) char dynsm[];
    uint32_t sm0 = smem_u32(dynsm);

    int tid = threadIdx.x, lane = tid & 31, warp = tid >> 5;
    int m0 = blockIdx.y * 64, n0 = blockIdx.x * 128, z = blockIdx.z;
    int wm = warp >> 2, wn = warp & 3;
    int g = lane >> 2, t4 = lane & 3;

    float acc[2][4][4];
#pragma unroll
    for (int i = 0; i < 2; i++)
#pragma unroll
        for (int j = 0; j < 4; j++)
#pragma unroll
            for (int q = 0; q < 4; q++) acc[i][j][q] = 0.f;

    int T = p.K() >> 5;
#pragma unroll
    for (int s = 0; s < GS - 1; s++) {
        p.cpA(stA(sm0, s), m0, s * 32, tid, z);
        p.cpB(stB(sm0, s), n0, s * 32, tid, z);
        cp_commit();
    }

    int a_r = lane & 15, a_c = (lane >> 4) << 3;
    int b_kr = lane & 15, b_nc = (lane >> 4) << 3;

    int cur = 0, nxt = GS - 1;
    for (int t = 0; t < T; t++) {
        cp_wait<GS - 2>();
        __syncthreads();
        if (t + GS - 1 < T) {
            p.cpA(stA(sm0, nxt), m0, (t + GS - 1) * 32, tid, z);
            p.cpB(stB(sm0, nxt), n0, (t + GS - 1) * 32, tid, z);
        }
        cp_commit();

        uint32_t ab = stA(sm0, cur);
        uint32_t bb = stB(sm0, cur);
        cur = (cur + 1 == GS) ? 0 : cur + 1;
        nxt = (nxt + 1 == GS) ? 0 : nxt + 1;

        uint32_t af[2][2][4];
        uint32_t bf[2][4][2];
#pragma unroll
        for (int ks = 0; ks < 2; ks++) {
            int kk = ks * 16;
#pragma unroll
            for (int mi = 0; mi < 2; mi++) {
                uint32_t addr = ab +
                    (uint32_t)(((wm * 32 + mi * 16 + a_r) * ASTR + kk + a_c) * 2);
                ldm_x4(af[ks][mi], addr);
            }
#pragma unroll
            for (int nb = 0; nb < 2; nb++) {
                uint32_t r[4];
                uint32_t addr = bb +
                    (uint32_t)(((kk + b_kr) * BSTR + wn * 32 + nb * 16 + b_nc) * 2);
                ldm_x4t(r, addr);
                bf[ks][nb * 2][0] = r[0]; bf[ks][nb * 2][1] = r[1];
                bf[ks][nb * 2 + 1][0] = r[2]; bf[ks][nb * 2 + 1][1] = r[3];
            }
        }
#pragma unroll
        for (int ks = 0; ks < 2; ks++)
#pragma unroll
            for (int mi = 0; mi < 2; mi++)
#pragma unroll
                for (int nj = 0; nj < 4; nj++)
                    mma_f16(acc[mi][nj], af[ks][mi], bf[ks][nj]);
    }
#pragma unroll
    for (int mi = 0; mi < 2; mi++) {
        int r0 = m0 + wm * 32 + mi * 16 + g;
#pragma unroll
        for (int nj = 0; nj < 4; nj++) {
            int c = n0 + wn * 32 + nj * 8 + 2 * t4;
            p.store2(r0, c, acc[mi][nj][0], acc[mi][nj][1], z);
            p.store2(r0 + 8, c, acc[mi][nj][2], acc[mi][nj][3], z);
        }
    }
}

// ---------------- wide fp16 GEMM: 64x256 tile, warptile 32x64, BK=32, 4-stage ----------------
constexpr int BSTRW = 264;
constexpr int B_STW = 32 * BSTRW;
constexpr int STG_HW = A_ST + B_STW;     // 2560 + 8448 = 11008 halves
constexpr int GSW = 4;
constexpr size_t GEMW_SMEM = (size_t)GSW * STG_HW * sizeof(__half); // 88064 B

DEV uint32_t stAW(uint32_t sm0, int s) { return sm0 + (uint32_t)(s * STG_HW * 2); }
DEV uint32_t stBW(uint32_t sm0, int s) { return sm0 + (uint32_t)((s * STG_HW + A_ST) * 2); }

DEV void cpBW_dense(uint32_t base, const __half* __restrict__ W, size_t ldn,
                    int n0, int k0, int tid) {
    // 32 rows x 256 halves = 512 16-half chunks; thread covers chunks tid, tid+256
    int r0w = tid >> 4, nh = (tid & 15) << 4;
    const __half* s0 = W + (size_t)(k0 + r0w) * ldn + n0 + nh;
    uint32_t d0 = base + (uint32_t)((r0w * BSTRW + nh) * 2);
    cp16(d0, s0);
    cp16(d0 + 16, s0 + 8);
    int r1w = r0w + 16;
    const __half* s1 = W + (size_t)(k0 + r1w) * ldn + n0 + nh;
    uint32_t d1 = base + (uint32_t)((r1w * BSTRW + nh) * 2);
    cp16(d1, s1);
    cp16(d1 + 16, s1 + 8);
}

template <class P>
__global__ __launch_bounds__(256, 2) void gemm_w(P p) {
    if (p.skip()) return;
    extern __shared__ __align__(16) char dynsm[];
    uint32_t sm0 = smem_u32(dynsm);

    int tid = threadIdx.x, lane = tid & 31, warp = tid >> 5;
    int m0 = blockIdx.y * 64, n0 = blockIdx.x * 256, z = blockIdx.z;
    int wm = warp >> 2, wn = warp & 3;   // warptile 32x64
    int g = lane >> 2, t4 = lane & 3;

    float acc[2][8][4];
#pragma unroll
    for (int i = 0; i < 2; i++)
#pragma unroll
        for (int j = 0; j < 8; j++)
#pragma unroll
            for (int q = 0; q < 4; q++) acc[i][j][q] = 0.f;

    int T = p.K() >> 5;
#pragma unroll
    for (int s = 0; s < GSW - 1; s++) {
        p.cpA(stAW(sm0, s), m0, s * 32, tid, z);
        p.cpB(stBW(sm0, s), n0, s * 32, tid, z);
        cp_commit();
    }

    int a_r = lane & 15, a_c = (lane >> 4) << 3;
    int b_kr = lane & 15, b_nc = (lane >> 4) << 3;

    int cur = 0, nxt = GSW - 1;
    for (int t = 0; t < T; t++) {
        cp_wait<GSW - 2>();
        __syncthreads();
        if (t + GSW - 1 < T) {
            p.cpA(stAW(sm0, nxt), m0, (t + GSW - 1) * 32, tid, z);
            p.cpB(stBW(sm0, nxt), n0, (t + GSW - 1) * 32, tid, z);
        }
        cp_commit();

        uint32_t ab = stAW(sm0, cur);
        uint32_t bb = stBW(sm0, cur);
        cur = (cur + 1 == GSW) ? 0 : cur + 1;
        nxt = (nxt + 1 == GSW) ? 0 : nxt + 1;
#pragma unroll
        for (int ks = 0; ks < 2; ks++) {
            int kk = ks * 16;
            uint32_t af[2][4];
#pragma unroll
            for (int mi = 0; mi < 2; mi++) {
                uint32_t addr = ab +
                    (uint32_t)(((wm * 32 + mi * 16 + a_r) * ASTR + kk + a_c) * 2);
                ldm_x4(af[mi], addr);
            }
            uint32_t bf[8][2];
#pragma unroll
            for (int nb = 0; nb < 4; nb++) {
                uint32_t r[4];
                uint32_t addr = bb +
                    (uint32_t)(((kk + b_kr) * BSTRW + wn * 64 + nb * 16 + b_nc) * 2);
                ldm_x4t(r, addr);
                bf[nb * 2][0] = r[0]; bf[nb * 2][1] = r[1];
                bf[nb * 2 + 1][0] = r[2]; bf[nb * 2 + 1][1] = r[3];
            }
#pragma unroll
            for (int mi = 0; mi < 2; mi++)
#pragma unroll
                for (int nj = 0; nj < 8; nj++)
                    mma_f16(acc[mi][nj], af[mi], bf[nj]);
        }
    }
#pragma unroll
    for (int mi = 0; mi < 2; mi++) {
        int r0 = m0 + wm * 32 + mi * 16 + g;
#pragma unroll
        for (int nj = 0; nj < 8; nj++) {
            int c = n0 + wn * 64 + nj * 8 + 2 * t4;
            p.store2(r0, c, acc[mi][nj][0], acc[mi][nj][1], z);
            p.store2(r0 + 8, c, acc[mi][nj][2], acc[mi][nj][3], z);
        }
    }
}

// ================= functors =================

struct ConvProb {
    const float* cb;
    const float* xres;
    DEV int K() const { return KC * Dc; }
    DEV bool skip() const { return false; }
    DEV void cpA(uint32_t base, int m0, int k0, int tid, int) const {
        int row = tid >> 2;
        int m = m0 + row;
        int b = m >> 11, s = m & 2047;
        int k = k0 + ((tid & 3) << 3);
        int kk = k >> 9, ci = k & 511;
        int sr = s + kk - 15;
        bool ok = (unsigned)sr < (unsigned)Sc;
        const __half* src = &hh1[(size_t)((b << 11) + (ok ? sr : 0)) * Dc + ci];
        cp16z(base + (uint32_t)((row * ASTR + ((tid & 3) << 3)) * 2), src, ok);
    }
    DEV void cpB(uint32_t base, int n0, int k0, int tid, int) const {
        cpB_dense(base, hck, Dc, n0, k0, tid);
    }
    DEV void store2(int m, int c, float v0, float v1, int) const {
        size_t o = (size_t)m * Dc + c;
        g_x1[o]     = gelu_f(v0 + cb[c])     + xres[o];
        g_x1[o + 1] = gelu_f(v1 + cb[c + 1]) + xres[o + 1];
    }
};

// fused QKV: A = hh2, B = hwqkv [512][1536]; wide kernel
struct QKVProb {
    const float* b[3];
    DEV int K() const { return Dc; }
    DEV bool skip() const { return false; }
    DEV void cpA(uint32_t base, int m0, int k0, int tid, int) const {
        cpA_dense(base, hh2, Dc, m0, k0, tid);
    }
    DEV void cpB(uint32_t base, int n0, int k0, int tid, int) const {
        cpBW_dense(base, hwqkv, 3 * Dc, n0, k0, tid);
    }
    DEV void store2(int m, int c, float v0, float v1, int) const {
        int which = c >> 9, col = c & 511;
        __half* o = (which == 0) ? hq : (which == 1) ? hk : hv;
        const float* bias = b[which];
        size_t off = (size_t)m * Dc + col;
        o[off]     = __float2half(v0 + bias[col]);
        o[off + 1] = __float2half(v1 + bias[col + 1]);
    }
};

struct OutProb {
    const float* bo;
    DEV int K() const { return Dc; }
    DEV bool skip() const { return false; }
    DEV void cpA(uint32_t base, int m0, int k0, int tid, int) const {
        cpA_dense(base, ho, Dc, m0, k0, tid);
    }
    DEV void cpB(uint32_t base, int n0, int k0, int tid, int) const {
        cpB_dense(base, hwo, Dc, n0, k0, tid);
    }
    DEV void store2(int m, int c, float v0, float v1, int) const {
        size_t o = (size_t)m * Dc + c;
        float r0 = v0 + bo[c]     + g_x1[o];
        float r1 = v1 + bo[c + 1] + g_x1[o + 1];
        g_x2[o] = r0;     g_x2[o + 1] = r1;
        hx2[o] = __float2half(r0);
        hx2[o + 1] = __float2half(r1);
    }
};

// MoE1 on wide kernel: N-tile 256 over FF=2048
struct Moe1Prob {
    const float* b1;
    DEV int K() const { return Dc; }
    DEV bool skip() const { return (int)(blockIdx.y * 64) >= g_cnt[blockIdx.z >> 1]; }
    DEV void cpA(uint32_t base, int m0, int k0, int tid, int z) const {
        int g = z >> 1;
        int row = tid >> 2;
        int i = m0 + row;
        bool ok = i < g_cnt[g];
        int tok = ok ? g_perm[(g << 12) + i] : 0;
        int kh = (tid & 3) << 3;
        cp16z(base + (uint32_t)((row * ASTR + kh) * 2),
              &hx2[(size_t)tok * Dc + k0 + kh], ok);
    }
    DEV void cpB(uint32_t base, int n0, int k0, int tid, int z) const {
        cpBW_dense(base, hw1 + (size_t)z * Dc * FFc, FFc, n0, k0, tid);
    }
    DEV void store2(int idx, int c, float v0, float v1, int z) const {
        int g = z >> 1, e = z & 1;
        if (idx >= g_cnt[g]) return;
        int tok = g_perm[(g << 12) + idx];
        size_t o = (size_t)tok * (Ec * FFc) + (e << 11) + c;
        const float* bb = &b1[(size_t)z * FFc + c];
        hhid[o]     = __float2half(gelu_f(v0 + bb[0]));
        hhid[o + 1] = __float2half(gelu_f(v1 + bb[1]));
    }
};

struct Moe2Prob {
    const float* b2;
    float* out;
    DEV int K() const { return Ec * FFc; }
    DEV bool skip() const { return (int)(blockIdx.y * 64) >= g_cnt[blockIdx.z]; }
    DEV void cpA(uint32_t base, int m0, int k0, int tid, int z) const {
        int g = z;
        int row = tid >> 2;
        int i = m0 + row;
        bool ok = i < g_cnt[g];
        int tok = ok ? g_perm[(g << 12) + i] : 0;
        int kh = (tid & 3) << 3;
        cp16z(base + (uint32_t)((row * ASTR + kh) * 2),
              &hhid[(size_t)tok * (Ec * FFc) + k0 + kh], ok);
    }
    DEV void cpB(uint32_t base, int n0, int k0, int tid, int z) const {
        cpB_dense(base, hw2 + (size_t)z * Ec * FFc * Dc, Dc, n0, k0, tid);
    }
    DEV void store2(int idx, int c, float v0, float v1, int z) const {
        int g = z;
        if (idx >= g_cnt[g]) return;
        int tok = g_perm[(g << 12) + idx];
        size_t o = (size_t)tok * Dc + c;
        float bs0 = b2[(size_t)(g * 2) * Dc + c] + b2[(size_t)(g * 2 + 1) * Dc + c];
        float bs1 = b2[(size_t)(g * 2) * Dc + c + 1] + b2[(size_t)(g * 2 + 1) * Dc + c + 1];
        out[o]     = 0.5f * v0 + 0.5f * bs0 + g_x2[o];
        out[o + 1] = 0.5f * v1 + 0.5f * bs1 + g_x2[o + 1];
    }
};

// ================= launch =================
template <class P>
static void launch_gemm(dim3 grid, const P& p) {
    cudaFuncSetAttribute(gemm_h<P>, cudaFuncAttributeMaxDynamicSharedMemorySize,
                         (int)GEMM_SMEM);
    gemm_h<P><<<grid, 256, GEMM_SMEM>>>(p);
}
template <class P>
static void launch_gemw(dim3 grid, const P& p) {
    cudaFuncSetAttribute(gemm_w<P>, cudaFuncAttributeMaxDynamicSharedMemorySize,
                         (int)GEMW_SMEM);
    gemm_w<P><<<grid, 256, GEMW_SMEM>>>(p);
}

static void cvt_s(const float* s, __half* d, size_t n, cudaStream_t st) {
    int n4 = (int)(n >> 2);
    int grid = (n4 + 255) / 256;
    if (grid > 1184) grid = 1184;
    cvt_kernel<<<grid, 256, 0, st>>>(s, d, n4);
}
static void cvts_s(const float* s, __half* d, int ncols, int dstride, int coloff,
                   size_t n, cudaStream_t st) {
    int n4 = (int)(n >> 2);
    int grid = (n4 + 255) / 256;
    if (grid > 1184) grid = 1184;
    cvts_kernel<<<grid, 256, 0, st>>>(s, d, ncols, dstride, coloff, n4);
}

extern "C" void kernel_launch(void* const* d_in, const int* in_sizes, int n_in,
                              void* d_out, int out_size) {
    const float* x    = (const float*)d_in[0];
    const int*   gid  = (const int*)d_in[1];
    const float* ln1s = (const float*)d_in[2];
    const float* ln1b = (const float*)d_in[3];
    const float* ck   = (const float*)d_in[4];
    const float* cb   = (const float*)d_in[5];
    const float* ln2s = (const float*)d_in[6];
    const float* ln2b = (const float*)d_in[7];
    const float* wq   = (const float*)d_in[8];
    const float* bq   = (const float*)d_in[9];
    const float* wk   = (const float*)d_in[10];
    const float* bk   = (const float*)d_in[11];
    const float* wv   = (const float*)d_in[12];
    const float* bv   = (const float*)d_in[13];
    const float* wo   = (const float*)d_in[14];
    const float* bo   = (const float*)d_in[15];
    const float* w1   = (const float*)d_in[16];
    const float* b1   = (const float*)d_in[17];
    const float* w2   = (const float*)d_in[18];
    const float* b2   = (const float*)d_in[19];
    float* out = (float*)d_out;

    __half* d_hck;   cudaGetSymbolAddress((void**)&d_hck, hck);
    __half* d_hwqkv; cudaGetSymbolAddress((void**)&d_hwqkv, hwqkv);
    __half* d_hwo;   cudaGetSymbolAddress((void**)&d_hwo, hwo);
    __half* d_hw1;   cudaGetSymbolAddress((void**)&d_hw1, hw1);
    __half* d_hw2;   cudaGetSymbolAddress((void**)&d_hw2, hw2);

    cudaStream_t s1;
    cudaStreamCreateWithFlags(&s1, cudaStreamNonBlocking);
    cudaEvent_t evF, evLn1, evQKVw, evWo, evMoe1, evW2;
    cudaEventCreateWithFlags(&evF, cudaEventDisableTiming);
    cudaEventCreateWithFlags(&evLn1, cudaEventDisableTiming);
    cudaEventCreateWithFlags(&evQKVw, cudaEventDisableTiming);
    cudaEventCreateWithFlags(&evWo, cudaEventDisableTiming);
    cudaEventCreateWithFlags(&evMoe1, cudaEventDisableTiming);
    cudaEventCreateWithFlags(&evW2, cudaEventDisableTiming);

    cudaEventRecord(evF, 0);
    cudaStreamWaitEvent(s1, evF, 0);

    // ---- side stream ----
    ln_kernel<0><<<Nc, 256, 0, s1>>>(x, ln1s, ln1b);
    cudaEventRecord(evLn1, s1);
    cvts_s(wq, d_hwqkv, Dc, 3 * Dc, 0,      (size_t)Dc * Dc, s1);
    cvts_s(wk, d_hwqkv, Dc, 3 * Dc, Dc,     (size_t)Dc * Dc, s1);
    cvts_s(wv, d_hwqkv, Dc, 3 * Dc, 2 * Dc, (size_t)Dc * Dc, s1);
    cudaEventRecord(evQKVw, s1);
    cvt_s(wo, d_hwo, (size_t)Dc * Dc, s1);
    cudaEventRecord(evWo, s1);
    zero_cnt_kernel<<<1, 32, 0, s1>>>();
    scatter_kernel<<<Nc / 256, 256, 0, s1>>>(gid);
    cvt_s(w1, d_hw1, (size_t)Gc * Ec * Dc * FFc, s1);
    cudaEventRecord(evMoe1, s1);
    cvt_s(w2, d_hw2, (size_t)Gc * Ec * FFc * Dc, s1);
    cudaEventRecord(evW2, s1);

    // ---- main stream ----
    cvt_s(ck, d_hck, (size_t)KC * Dc * Dc, 0);
    cudaStreamWaitEvent(0, evLn1, 0);
    {
        ConvProb p{cb, x};
        launch_gemm(dim3(Dc / 128, Nc / 64, 1), p);
    }
    ln_kernel<1><<<Nc, 256>>>(x, ln2s, ln2b);
    cudaStreamWaitEvent(0, evQKVw, 0);
    {
        QKVProb p;
        p.b[0] = bq; p.b[1] = bk; p.b[2] = bv;
        launch_gemw(dim3(3 * Dc / 256, Nc / 64, 1), p);
    }
    cudaFuncSetAttribute(flash_kernel, cudaFuncAttributeMaxDynamicSharedMemorySize,
                         (int)FLASH_SMEM);
    flash_kernel<<<dim3(Sc / 128, Bc * Hc), 256, FLASH_SMEM>>>();
    cudaStreamWaitEvent(0, evWo, 0);
    {
        OutProb p{bo};
        launch_gemm(dim3(Dc / 128, Nc / 64, 1), p);
    }
    cudaStreamWaitEvent(0, evMoe1, 0);
    {
        Moe1Prob p{b1};
        launch_gemw(dim3(FFc / 256, Nc / 64, Gc * Ec), p);
    }
    cudaStreamWaitEvent(0, evW2, 0);
    {
        Moe2Prob p{b2, out};
        launch_gemm(dim3(Dc / 128, Nc / 64, Gc), p);
    }
}